// round 5
// baseline (speedup 1.0000x reference)
#include <cuda_runtime.h>
#include <math.h>

// Problem constants (from reference)
#define IN_F   4096
#define HID    512
#define NCLS   10
#define NODES_MAX 20000
#define MAX_E  700000

// ---------------- device scratch (no allocation allowed) ----------------
__device__ int   g_shift;                    // 0 = int32 edges, 1 = int64 edges
__device__ int   g_deg[NODES_MAX];
__device__ float g_dinv[NODES_MAX];
__device__ int   g_rowptr[NODES_MAX + 1];
__device__ int   g_cursor[NODES_MAX];
__device__ int   g_col[MAX_E];
__device__ float g_h1[(long long)NODES_MAX * HID];   // x @ W1
__device__ float g_r1[(long long)NODES_MAX * HID];   // relu(Â h1 + b1)
__device__ float g_h2[(long long)NODES_MAX * NCLS];  // r1 @ W2

// ---------------- f32x2 packed-FMA helpers (FFMA2, PTX-only path) -------
__device__ __forceinline__ void ffma2(unsigned long long& d,
                                      unsigned long long a,
                                      unsigned long long b) {
    asm("fma.rn.f32x2 %0, %1, %2, %0;" : "+l"(d) : "l"(a), "l"(b));
}
__device__ __forceinline__ unsigned long long pack2(float x) {
    unsigned long long r;
    asm("mov.b64 %0, {%1, %1};" : "=l"(r) : "f"(x));
    return r;
}
__device__ __forceinline__ float2 unpack2(unsigned long long v) {
    float2 r;
    asm("mov.b64 {%0, %1}, %2;" : "=f"(r.x), "=f"(r.y) : "l"(v));
    return r;
}

// ---------------- edge dtype detection ----------------------------------
// int64 little-endian buffer of small nonneg values => every odd 32-bit word 0.
__global__ void k_detect(const int* __restrict__ ei, int E) {
    __shared__ int s_any;
    if (threadIdx.x == 0) s_any = 0;
    __syncthreads();
    int m = E < 2048 ? E : 2048;
    int nz = 0;
    for (int i = threadIdx.x; i < m; i += blockDim.x) nz |= ei[2 * i + 1];
    if (nz) s_any = 1;   // benign race: any writer sets 1
    __syncthreads();
    if (threadIdx.x == 0) g_shift = (s_any == 0) ? 1 : 0;
}

__global__ void k_zero(int n) {
    int i = blockIdx.x * blockDim.x + threadIdx.x;
    if (i < n) g_deg[i] = 0;
}

__global__ void k_count(const int* __restrict__ ei, int E) {
    int e = blockIdx.x * blockDim.x + threadIdx.x;
    if (e < E) {
        int sh = g_shift;
        int d = ei[(E + e) << sh];
        atomicAdd(&g_deg[d], 1);
    }
}

__global__ void k_dinv(int n) {
    int i = blockIdx.x * blockDim.x + threadIdx.x;
    if (i < n) {
        float df = (float)(g_deg[i] + 1);   // +1 self loop
        g_dinv[i] = 1.0f / sqrtf(df);
    }
}

// single-block exclusive scan of g_deg -> g_rowptr, init g_cursor
__global__ void k_scan(int n) {
    __shared__ int s[1024];
    __shared__ int carry_s;
    int tid = threadIdx.x;
    if (tid == 0) carry_s = 0;
    __syncthreads();
    for (int base = 0; base < n; base += 1024) {
        int i = base + tid;
        int v = (i < n) ? g_deg[i] : 0;
        s[tid] = v;
        __syncthreads();
        for (int off = 1; off < 1024; off <<= 1) {
            int t = (tid >= off) ? s[tid - off] : 0;
            __syncthreads();
            s[tid] += t;
            __syncthreads();
        }
        int carry = carry_s;
        __syncthreads();
        if (tid == 1023) carry_s = carry + s[1023];
        if (i < n) {
            int excl = carry + s[tid] - v;
            g_rowptr[i] = excl;
            g_cursor[i] = excl;
        }
        __syncthreads();
    }
    if (tid == 0) g_rowptr[n] = carry_s;
}

__global__ void k_fill(const int* __restrict__ ei, int E) {
    int e = blockIdx.x * blockDim.x + threadIdx.x;
    if (e < E) {
        int sh = g_shift;
        int s = ei[e << sh];
        int d = ei[(E + e) << sh];
        int pos = atomicAdd(&g_cursor[d], 1);
        g_col[pos] = s;
    }
}

// ---------------- GEMM1: h1 = x @ W1   (M x 4096 @ 4096 x 512) ----------
// 128x128 block tile, BK=16, 256 threads, 8x8 micro-tile via f32x2 FMAs.
__global__ __launch_bounds__(256, 2)
void k_gemm1(const float* __restrict__ A, const float* __restrict__ B, int M) {
    __shared__ float As[16][132];   // stride 132 keeps float4 alignment, reduces store conflicts
    __shared__ float Bs[16][128];

    int tid = threadIdx.x;
    int m0 = blockIdx.y * 128;
    int n0 = blockIdx.x * 128;
    int tx = tid & 15, ty = tid >> 4;

    unsigned long long acc[8][4];
#pragma unroll
    for (int i = 0; i < 8; i++)
#pragma unroll
        for (int j = 0; j < 4; j++) acc[i][j] = 0ull;

    int arow0 = tid >> 2;
    int akk   = (tid & 3) << 2;
    int bkk   = tid >> 5;
    int bcc   = (tid & 31) << 2;

    for (int kt = 0; kt < IN_F; kt += 16) {
        // A tile: 128 rows x 16 k, transposed into As[k][row]
#pragma unroll
        for (int it = 0; it < 2; it++) {
            int row = arow0 + (it << 6);
            int gr  = m0 + row;
            float4 v = make_float4(0.f, 0.f, 0.f, 0.f);
            if (gr < M)
                v = *(const float4*)&A[(long long)gr * IN_F + kt + akk];
            As[akk + 0][row] = v.x;
            As[akk + 1][row] = v.y;
            As[akk + 2][row] = v.z;
            As[akk + 3][row] = v.w;
        }
        // B tile: 16 k-rows x 128 cols
#pragma unroll
        for (int it = 0; it < 2; it++) {
            int kk = bkk + (it << 3);
            *(float4*)&Bs[kk][bcc] =
                *(const float4*)&B[(long long)(kt + kk) * HID + n0 + bcc];
        }
        __syncthreads();

#pragma unroll
        for (int k = 0; k < 16; k++) {
            float4 a0 = *(const float4*)&As[k][ty * 8];
            float4 a1 = *(const float4*)&As[k][ty * 8 + 4];
            ulonglong2 b01 = *(const ulonglong2*)&Bs[k][tx * 8];
            ulonglong2 b23 = *(const ulonglong2*)&Bs[k][tx * 8 + 4];
            unsigned long long bb0 = b01.x, bb1 = b01.y, bb2 = b23.x, bb3 = b23.y;
            float av[8] = {a0.x, a0.y, a0.z, a0.w, a1.x, a1.y, a1.z, a1.w};
#pragma unroll
            for (int i = 0; i < 8; i++) {
                unsigned long long aa = pack2(av[i]);
                ffma2(acc[i][0], aa, bb0);
                ffma2(acc[i][1], aa, bb1);
                ffma2(acc[i][2], aa, bb2);
                ffma2(acc[i][3], aa, bb3);
            }
        }
        __syncthreads();
    }

#pragma unroll
    for (int i = 0; i < 8; i++) {
        int gr = m0 + ty * 8 + i;
        if (gr < M) {
            float2 c0 = unpack2(acc[i][0]);
            float2 c1 = unpack2(acc[i][1]);
            float2 c2 = unpack2(acc[i][2]);
            float2 c3 = unpack2(acc[i][3]);
            float4 o0 = make_float4(c0.x, c0.y, c1.x, c1.y);
            float4 o1 = make_float4(c2.x, c2.y, c3.x, c3.y);
            long long off = (long long)gr * HID + n0 + tx * 8;
            *(float4*)&g_h1[off]     = o0;
            *(float4*)&g_h1[off + 4] = o1;
        }
    }
}

// ---------------- SpMM1: r1 = relu( dinv_d * (sum dinv_s h1[s]) + b1 ) ---
// one block of 128 threads per dst row; each thread owns 4 contiguous cols
__global__ void k_spmm1(const float* __restrict__ b1) {
    int row = blockIdx.x;
    int c = threadIdx.x << 2;
    float di = g_dinv[row];

    float4 v = *(const float4*)&g_h1[(long long)row * HID + c];
    float4 acc;
    acc.x = di * v.x; acc.y = di * v.y; acc.z = di * v.z; acc.w = di * v.w;

    int p0 = g_rowptr[row], p1 = g_rowptr[row + 1];
    for (int p = p0; p < p1; ++p) {
        int s = g_col[p];
        float w = g_dinv[s];
        float4 u = *(const float4*)&g_h1[(long long)s * HID + c];
        acc.x += w * u.x; acc.y += w * u.y; acc.z += w * u.z; acc.w += w * u.w;
    }
    float4 bb = *(const float4*)&b1[c];
    acc.x = fmaxf(acc.x * di + bb.x, 0.f);
    acc.y = fmaxf(acc.y * di + bb.y, 0.f);
    acc.z = fmaxf(acc.z * di + bb.z, 0.f);
    acc.w = fmaxf(acc.w * di + bb.w, 0.f);
    *(float4*)&g_r1[(long long)row * HID + c] = acc;
}

// ---------------- GEMM2: h2 = r1 @ W2  (M x 512 @ 512 x 10) -------------
__global__ void k_gemm2(const float* __restrict__ W2, int Nn) {
    __shared__ float w[HID * NCLS];
    for (int i = threadIdx.x; i < HID * NCLS; i += blockDim.x) w[i] = W2[i];
    __syncthreads();
    int row = blockIdx.x * blockDim.x + threadIdx.x;
    if (row >= Nn) return;
    float acc[NCLS];
#pragma unroll
    for (int j = 0; j < NCLS; j++) acc[j] = 0.f;
    const float4* xr = (const float4*)&g_r1[(long long)row * HID];
#pragma unroll 4
    for (int k4 = 0; k4 < HID / 4; k4++) {
        float4 x = xr[k4];
        const float* w0 = &w[(k4 * 4) * NCLS];
#pragma unroll
        for (int j = 0; j < NCLS; j++)
            acc[j] += x.x * w0[j] + x.y * w0[NCLS + j] +
                      x.z * w0[2 * NCLS + j] + x.w * w0[3 * NCLS + j];
    }
#pragma unroll
    for (int j = 0; j < NCLS; j++) g_h2[(long long)row * NCLS + j] = acc[j];
}

// ---------------- SpMM2 + bias + log_softmax (warp per row) -------------
__global__ void k_spmm2(const float* __restrict__ b2, float* __restrict__ out, int Nn) {
    int row = (blockIdx.x * blockDim.x + threadIdx.x) >> 5;
    int lane = threadIdx.x & 31;
    if (row >= Nn) return;

    float di = g_dinv[row];
    float acc = 0.f;
    if (lane < NCLS) acc = di * g_h2[(long long)row * NCLS + lane];

    int p0 = g_rowptr[row], p1 = g_rowptr[row + 1];
    for (int p = p0; p < p1; ++p) {
        int s = g_col[p];
        float w = g_dinv[s];
        if (lane < NCLS) acc += w * g_h2[(long long)s * NCLS + lane];
    }
    acc = acc * di + ((lane < NCLS) ? b2[lane] : 0.f);

    float v = (lane < NCLS) ? acc : -3.4e38f;
#pragma unroll
    for (int o = 16; o > 0; o >>= 1) v = fmaxf(v, __shfl_xor_sync(0xffffffffu, v, o));
    float ex = (lane < NCLS) ? expf(acc - v) : 0.f;
#pragma unroll
    for (int o = 16; o > 0; o >>= 1) ex += __shfl_xor_sync(0xffffffffu, ex, o);
    float lse = logf(ex);
    if (lane < NCLS) out[(long long)row * NCLS + lane] = acc - v - lse;
}

// ---------------- launch ---------------------------------------------------
extern "C" void kernel_launch(void* const* d_in, const int* in_sizes, int n_in,
                              void* d_out, int out_size) {
    const float* x  = (const float*)d_in[0];
    const int*   ei = (const int*)d_in[1];
    const float* W1 = (const float*)d_in[2];
    const float* b1 = (const float*)d_in[3];
    const float* W2 = (const float*)d_in[4];
    const float* b2 = (const float*)d_in[5];
    float* out = (float*)d_out;

    int Nn = in_sizes[0] / IN_F;          // 20000
    int E  = in_sizes[1] / 2;             // element count of edge_index / 2

    k_detect<<<1, 256>>>(ei, E);
    k_zero  <<<(Nn + 255) / 256, 256>>>(Nn);
    k_count <<<(E + 255) / 256, 256>>>(ei, E);
    k_dinv  <<<(Nn + 255) / 256, 256>>>(Nn);
    k_scan  <<<1, 1024>>>(Nn);
    k_fill  <<<(E + 255) / 256, 256>>>(ei, E);

    dim3 g1(HID / 128, (Nn + 127) / 128);
    k_gemm1 <<<g1, 256>>>(x, W1, Nn);
    k_spmm1 <<<Nn, 128>>>(b1);
    k_gemm2 <<<(Nn + 127) / 128, 128>>>(W2, Nn);
    k_spmm2 <<<(Nn * 32 + 127) / 128, 128>>>(b2, out, Nn);
}

// round 7
// speedup vs baseline: 2.3434x; 2.3434x over previous
#include <cuda_runtime.h>
#include <cuda_bf16.h>
#include <math.h>

// Problem constants
#define IN_F   4096
#define HID    512
#define NCLS   10
#define NODES_MAX 20000
#define MAX_E  700000
#define NK64   (IN_F / 64)          // 64 K-stages of 64

// ---------------- device scratch (no allocation allowed) ----------------
__device__ int   g_shift;
__device__ int   g_deg[NODES_MAX];
__device__ float g_dinv[NODES_MAX];
__device__ int   g_rowptr[NODES_MAX + 1];
__device__ int   g_cursor[NODES_MAX];
__device__ int   g_col[MAX_E];
__device__ float g_h1[(long long)NODES_MAX * HID];   // conv1 dense result
__device__ float g_r1[(long long)NODES_MAX * HID];   // relu(A_hat h1 + b1)
__device__ float g_h2[(long long)NODES_MAX * NCLS];
// bf16 split copies for tensor-core GEMM1
__device__ __nv_bfloat16 g_xhi[(long long)NODES_MAX * IN_F];
__device__ __nv_bfloat16 g_xlo[(long long)NODES_MAX * IN_F];
__device__ __nv_bfloat16 g_w1hi[(long long)HID * IN_F];   // transposed [n][k]
__device__ __nv_bfloat16 g_w1lo[(long long)HID * IN_F];

// ---------------- PTX helpers (baseline sm_80+ ISA only) -----------------
__device__ __forceinline__ unsigned smem_u32(const void* p) {
    unsigned a;
    asm("{ .reg .u64 t; cvta.to.shared.u64 t, %1; cvt.u32.u64 %0, t; }"
        : "=r"(a) : "l"(p));
    return a;
}
__device__ __forceinline__ void ldsm4(unsigned* r, unsigned addr) {
    asm volatile("ldmatrix.sync.aligned.m8n8.x4.shared.b16 {%0,%1,%2,%3}, [%4];"
                 : "=r"(r[0]), "=r"(r[1]), "=r"(r[2]), "=r"(r[3]) : "r"(addr));
}
__device__ __forceinline__ void mma16816(float* c, const unsigned* a, const unsigned* b) {
    asm volatile(
        "mma.sync.aligned.m16n8k16.row.col.f32.bf16.bf16.f32 "
        "{%0,%1,%2,%3}, {%4,%5,%6,%7}, {%8,%9}, {%0,%1,%2,%3};"
        : "+f"(c[0]), "+f"(c[1]), "+f"(c[2]), "+f"(c[3])
        : "r"(a[0]), "r"(a[1]), "r"(a[2]), "r"(a[3]), "r"(b[0]), "r"(b[1]));
}
__device__ __forceinline__ void cpasync16(unsigned dst, const void* src, int ok) {
    int sz = ok ? 16 : 0;
    asm volatile("cp.async.cg.shared.global [%0], [%1], 16, %2;"
                 :: "r"(dst), "l"(src), "r"(sz) : "memory");
}
#define CP_COMMIT()  asm volatile("cp.async.commit_group;" ::: "memory")
#define CP_WAIT1()   asm volatile("cp.async.wait_group 1;" ::: "memory")
#define SW(o) ((o) ^ (((o) >> 3) & 0x70))

// ---------------- edge dtype detection ----------------------------------
__global__ void k_detect(const int* __restrict__ ei, int E) {
    __shared__ int s_any;
    if (threadIdx.x == 0) s_any = 0;
    __syncthreads();
    int m = E < 2048 ? E : 2048;
    int nz = 0;
    for (int i = threadIdx.x; i < m; i += blockDim.x) nz |= ei[2 * i + 1];
    if (nz) s_any = 1;
    __syncthreads();
    if (threadIdx.x == 0) g_shift = (s_any == 0) ? 1 : 0;
}
__global__ void k_zero(int n) {
    int i = blockIdx.x * blockDim.x + threadIdx.x;
    if (i < n) g_deg[i] = 0;
}
__global__ void k_count(const int* __restrict__ ei, int E) {
    int e = blockIdx.x * blockDim.x + threadIdx.x;
    if (e < E) {
        int sh = g_shift;
        int d = ei[(E + e) << sh];
        atomicAdd(&g_deg[d], 1);
    }
}
__global__ void k_dinv(int n) {
    int i = blockIdx.x * blockDim.x + threadIdx.x;
    if (i < n) g_dinv[i] = 1.0f / sqrtf((float)(g_deg[i] + 1));
}
__global__ void k_scan(int n) {
    __shared__ int s[1024];
    __shared__ int carry_s;
    int tid = threadIdx.x;
    if (tid == 0) carry_s = 0;
    __syncthreads();
    for (int base = 0; base < n; base += 1024) {
        int i = base + tid;
        int v = (i < n) ? g_deg[i] : 0;
        s[tid] = v;
        __syncthreads();
        for (int off = 1; off < 1024; off <<= 1) {
            int t = (tid >= off) ? s[tid - off] : 0;
            __syncthreads();
            s[tid] += t;
            __syncthreads();
        }
        int carry = carry_s;
        __syncthreads();
        if (tid == 1023) carry_s = carry + s[1023];
        if (i < n) {
            int excl = carry + s[tid] - v;
            g_rowptr[i] = excl;
            g_cursor[i] = excl;
        }
        __syncthreads();
    }
    if (tid == 0) g_rowptr[n] = carry_s;
}
__global__ void k_fill(const int* __restrict__ ei, int E) {
    int e = blockIdx.x * blockDim.x + threadIdx.x;
    if (e < E) {
        int sh = g_shift;
        int s = ei[e << sh];
        int d = ei[(E + e) << sh];
        int pos = atomicAdd(&g_cursor[d], 1);
        g_col[pos] = s;
    }
}

// ---------------- bf16 hi/lo conversion ---------------------------------
__global__ void k_convA(const float* __restrict__ x, long long total4) {
    long long i = (long long)blockIdx.x * blockDim.x + threadIdx.x;
    if (i >= total4) return;
    float4 v = ((const float4*)x)[i];
    __nv_bfloat16 h0 = __float2bfloat16(v.x), h1 = __float2bfloat16(v.y);
    __nv_bfloat16 h2 = __float2bfloat16(v.z), h3 = __float2bfloat16(v.w);
    __nv_bfloat16 l0 = __float2bfloat16(v.x - __bfloat162float(h0));
    __nv_bfloat16 l1 = __float2bfloat16(v.y - __bfloat162float(h1));
    __nv_bfloat16 l2 = __float2bfloat16(v.z - __bfloat162float(h2));
    __nv_bfloat16 l3 = __float2bfloat16(v.w - __bfloat162float(h3));
    __nv_bfloat162 a = {h0, h1}, b = {h2, h3}, c = {l0, l1}, d = {l2, l3};
    uint2 uh, ul;
    uh.x = *(unsigned*)&a; uh.y = *(unsigned*)&b;
    ul.x = *(unsigned*)&c; ul.y = *(unsigned*)&d;
    *(uint2*)&g_xhi[4 * i] = uh;
    *(uint2*)&g_xlo[4 * i] = ul;
}
__global__ void k_convW(const float* __restrict__ W1) {
    int idx = blockIdx.x * blockDim.x + threadIdx.x;
    if (idx >= IN_F * HID) return;
    int k = idx / HID, n = idx % HID;       // coalesced read of W1[k][n]
    float v = W1[idx];
    __nv_bfloat16 h = __float2bfloat16(v);
    g_w1hi[(long long)n * IN_F + k] = h;
    g_w1lo[(long long)n * IN_F + k] = __float2bfloat16(v - __bfloat162float(h));
}

// ---------------- GEMM1 via mma.sync bf16 (3-term split, fp32 acc) -------
// CTA tile M=128 x N=128, BK=64, 256 threads (8 warps, warp tile 32x64),
// SW128-swizzled SMEM, ldmatrix.x4 frags, cp.async double buffering.
#define TA_HI 0
#define TA_LO 16384
#define TB_HI 32768
#define TB_LO 49152
#define STAGE_BYTES 65536
#define GSMEM_TOTAL (2 * STAGE_BYTES)

__device__ __forceinline__ void load_stage(unsigned base, int kt, int m0, int n0,
                                           int M, int tid) {
    int k0 = kt * 64;
#pragma unroll
    for (int it = 0; it < 4; it++) {
        int ch = tid + it * 256;                // 1024 chunks of 16B per tile
        int r = ch >> 3, seg = ch & 7;
        unsigned so = SW(r * 128 + seg * 16);
        // A: rows m0..m0+127
        int gr = m0 + r;
        long long gia = (long long)gr * IN_F + k0 + seg * 8;
        int okA = gr < M;
        cpasync16(base + TA_HI + so, &g_xhi[gia], okA);
        cpasync16(base + TA_LO + so, &g_xlo[gia], okA);
        // B: n-rows n0..n0+127
        long long gib = (long long)(n0 + r) * IN_F + k0 + seg * 8;
        cpasync16(base + TB_HI + so, &g_w1hi[gib], 1);
        cpasync16(base + TB_LO + so, &g_w1lo[gib], 1);
    }
}

__global__ __launch_bounds__(256, 1)
void k_gemm1_mma(int M) {
    extern __shared__ __align__(128) char sm[];
    unsigned sb = smem_u32(sm);
    int tid = threadIdx.x, wid = tid >> 5, lane = tid & 31;
    int m0 = blockIdx.y * 128, n0 = blockIdx.x * 128;
    int wm = (wid >> 1) * 32;        // warp m-offset (0,32,64,96)
    int wn = (wid & 1) * 64;         // warp n-offset (0,64)

    float acc[2][8][4];
#pragma unroll
    for (int i = 0; i < 2; i++)
#pragma unroll
        for (int j = 0; j < 8; j++)
#pragma unroll
            for (int q = 0; q < 4; q++) acc[i][j][q] = 0.f;

    // precompute ldmatrix lane addressing (tile-local byte offsets)
    // A: lanes 0-15 -> rows (lane&15), lanes>=16 -> +8 cols (16B)
    unsigned a_row = wm + (lane & 15);
    unsigned a_cb  = (lane >> 4) * 16;
    // B: quad = lane>>3: (quad>>1)*8 row offset, (quad&1)*16B col offset
    unsigned b_rowbase = wn + ((lane >> 4) << 3) + (lane & 7);
    unsigned b_cb = ((lane >> 3) & 1) * 16;

    load_stage(sb, 0, m0, n0, M, tid);
    CP_COMMIT();

    for (int kt = 0; kt < NK64; kt++) {
        unsigned cur = sb + (kt & 1) * STAGE_BYTES;
        if (kt + 1 < NK64)
            load_stage(sb + ((kt + 1) & 1) * STAGE_BYTES, kt + 1, m0, n0, M, tid);
        CP_COMMIT();
        CP_WAIT1();
        __syncthreads();

#pragma unroll
        for (int ks = 0; ks < 4; ks++) {
            unsigned ahi[2][4], alo[2][4], bhi[4][4], blo[4][4];
            unsigned acb = ks * 32 + a_cb;
#pragma unroll
            for (int mf = 0; mf < 2; mf++) {
                unsigned off = SW((a_row + mf * 16) * 128 + acb);
                ldsm4(ahi[mf], cur + TA_HI + off);
                ldsm4(alo[mf], cur + TA_LO + off);
            }
            unsigned bcb = ks * 32 + b_cb;
#pragma unroll
            for (int f = 0; f < 4; f++) {
                unsigned off = SW((b_rowbase + f * 16) * 128 + bcb);
                ldsm4(bhi[f], cur + TB_HI + off);
                ldsm4(blo[f], cur + TB_LO + off);
            }
            // term 0: hi*hi
#pragma unroll
            for (int mf = 0; mf < 2; mf++)
#pragma unroll
                for (int f = 0; f < 4; f++) {
                    mma16816(acc[mf][2 * f],     ahi[mf], &bhi[f][0]);
                    mma16816(acc[mf][2 * f + 1], ahi[mf], &bhi[f][2]);
                }
            // term 1: hi*lo
#pragma unroll
            for (int mf = 0; mf < 2; mf++)
#pragma unroll
                for (int f = 0; f < 4; f++) {
                    mma16816(acc[mf][2 * f],     ahi[mf], &blo[f][0]);
                    mma16816(acc[mf][2 * f + 1], ahi[mf], &blo[f][2]);
                }
            // term 2: lo*hi
#pragma unroll
            for (int mf = 0; mf < 2; mf++)
#pragma unroll
                for (int f = 0; f < 4; f++) {
                    mma16816(acc[mf][2 * f],     alo[mf], &bhi[f][0]);
                    mma16816(acc[mf][2 * f + 1], alo[mf], &bhi[f][2]);
                }
        }
        __syncthreads();
    }

    // epilogue: direct STG.64 of accumulators
    int gID = lane >> 2, tig = lane & 3;
#pragma unroll
    for (int mf = 0; mf < 2; mf++) {
        int r0 = m0 + wm + mf * 16 + gID;
#pragma unroll
        for (int nf = 0; nf < 8; nf++) {
            int col = n0 + wn + nf * 8 + tig * 2;
            if (r0 < M)
                *(float2*)&g_h1[(long long)r0 * HID + col] =
                    make_float2(acc[mf][nf][0], acc[mf][nf][1]);
            if (r0 + 8 < M)
                *(float2*)&g_h1[(long long)(r0 + 8) * HID + col] =
                    make_float2(acc[mf][nf][2], acc[mf][nf][3]);
        }
    }
}

// ---------------- SpMM1: r1 = relu( dinv_d * (sum dinv_s h1[s]) + b1 ) ---
__global__ void k_spmm1(const float* __restrict__ b1) {
    int row = blockIdx.x;
    int c = threadIdx.x << 2;
    float di = g_dinv[row];

    float4 v = *(const float4*)&g_h1[(long long)row * HID + c];
    float4 acc;
    acc.x = di * v.x; acc.y = di * v.y; acc.z = di * v.z; acc.w = di * v.w;

    int p0 = g_rowptr[row], p1 = g_rowptr[row + 1];
    for (int p = p0; p < p1; ++p) {
        int s = g_col[p];
        float w = g_dinv[s];
        float4 u = *(const float4*)&g_h1[(long long)s * HID + c];
        acc.x += w * u.x; acc.y += w * u.y; acc.z += w * u.z; acc.w += w * u.w;
    }
    float4 bb = *(const float4*)&b1[c];
    acc.x = fmaxf(acc.x * di + bb.x, 0.f);
    acc.y = fmaxf(acc.y * di + bb.y, 0.f);
    acc.z = fmaxf(acc.z * di + bb.z, 0.f);
    acc.w = fmaxf(acc.w * di + bb.w, 0.f);
    *(float4*)&g_r1[(long long)row * HID + c] = acc;
}

// ---------------- GEMM2: h2 = r1 @ W2  (M x 512 @ 512 x 10) -------------
__global__ void k_gemm2(const float* __restrict__ W2, int Nn) {
    __shared__ float w[HID * NCLS];
    for (int i = threadIdx.x; i < HID * NCLS; i += blockDim.x) w[i] = W2[i];
    __syncthreads();
    int row = blockIdx.x * blockDim.x + threadIdx.x;
    if (row >= Nn) return;
    float acc[NCLS];
#pragma unroll
    for (int j = 0; j < NCLS; j++) acc[j] = 0.f;
    const float4* xr = (const float4*)&g_r1[(long long)row * HID];
#pragma unroll 4
    for (int k4 = 0; k4 < HID / 4; k4++) {
        float4 x = xr[k4];
        const float* w0 = &w[(k4 * 4) * NCLS];
#pragma unroll
        for (int j = 0; j < NCLS; j++)
            acc[j] += x.x * w0[j] + x.y * w0[NCLS + j] +
                      x.z * w0[2 * NCLS + j] + x.w * w0[3 * NCLS + j];
    }
#pragma unroll
    for (int j = 0; j < NCLS; j++) g_h2[(long long)row * NCLS + j] = acc[j];
}

// ---------------- SpMM2 + bias + log_softmax (warp per row) -------------
__global__ void k_spmm2(const float* __restrict__ b2, float* __restrict__ out, int Nn) {
    int row = (blockIdx.x * blockDim.x + threadIdx.x) >> 5;
    int lane = threadIdx.x & 31;
    if (row >= Nn) return;

    float di = g_dinv[row];
    float acc = 0.f;
    if (lane < NCLS) acc = di * g_h2[(long long)row * NCLS + lane];

    int p0 = g_rowptr[row], p1 = g_rowptr[row + 1];
    for (int p = p0; p < p1; ++p) {
        int s = g_col[p];
        float w = g_dinv[s];
        if (lane < NCLS) acc += w * g_h2[(long long)s * NCLS + lane];
    }
    acc = acc * di + ((lane < NCLS) ? b2[lane] : 0.f);

    float v = (lane < NCLS) ? acc : -3.4e38f;
#pragma unroll
    for (int o = 16; o > 0; o >>= 1) v = fmaxf(v, __shfl_xor_sync(0xffffffffu, v, o));
    float ex = (lane < NCLS) ? expf(acc - v) : 0.f;
#pragma unroll
    for (int o = 16; o > 0; o >>= 1) ex += __shfl_xor_sync(0xffffffffu, ex, o);
    float lse = logf(ex);
    if (lane < NCLS) out[(long long)row * NCLS + lane] = acc - v - lse;
}

// ---------------- launch ---------------------------------------------------
extern "C" void kernel_launch(void* const* d_in, const int* in_sizes, int n_in,
                              void* d_out, int out_size) {
    const float* x  = (const float*)d_in[0];
    const int*   ei = (const int*)d_in[1];
    const float* W1 = (const float*)d_in[2];
    const float* b1 = (const float*)d_in[3];
    const float* W2 = (const float*)d_in[4];
    const float* b2 = (const float*)d_in[5];
    float* out = (float*)d_out;

    int Nn = in_sizes[0] / IN_F;          // 20000
    int E  = in_sizes[1] / 2;

    k_detect<<<1, 256>>>(ei, E);
    k_zero  <<<(Nn + 255) / 256, 256>>>(Nn);
    k_count <<<(E + 255) / 256, 256>>>(ei, E);
    k_dinv  <<<(Nn + 255) / 256, 256>>>(Nn);
    k_scan  <<<1, 1024>>>(Nn);
    k_fill  <<<(E + 255) / 256, 256>>>(ei, E);

    long long total4 = (long long)Nn * IN_F / 4;
    k_convA<<<(unsigned)((total4 + 255) / 256), 256>>>(x, total4);
    k_convW<<<(IN_F * HID + 255) / 256, 256>>>(W1);

    cudaFuncSetAttribute(k_gemm1_mma, cudaFuncAttributeMaxDynamicSharedMemorySize,
                         GSMEM_TOTAL);
    dim3 g1(HID / 128, (Nn + 127) / 128);   // (4, 157)
    k_gemm1_mma<<<g1, 256, GSMEM_TOTAL>>>(Nn);

    k_spmm1 <<<Nn, 128>>>(b1);
    k_gemm2 <<<(Nn + 127) / 128, 128>>>(W2, Nn);
    k_spmm2 <<<(Nn * 32 + 127) / 128, 128>>>(b2, out, Nn);
}

// round 9
// speedup vs baseline: 2.6363x; 1.1250x over previous
#include <cuda_runtime.h>
#include <cuda_bf16.h>
#include <math.h>

// Problem constants
#define IN_F   4096
#define HID    512
#define NCLS   10
#define NODES_MAX 20000
#define MAX_E  700000
#define NK64   (IN_F / 64)          // 64 K-stages of 64

// ---------------- device scratch (no allocation allowed) ----------------
__device__ int   g_shift;
__device__ int   g_deg[NODES_MAX];
__device__ float g_dinv[NODES_MAX];
__device__ int   g_rowptr[NODES_MAX + 1];
__device__ int   g_cursor[NODES_MAX];
__device__ int   g_col[MAX_E];
__device__ float g_h1[(long long)NODES_MAX * HID];   // conv1 dense result
__device__ float g_r1[(long long)NODES_MAX * HID];   // relu(A_hat h1 + b1)
__device__ float g_h2[(long long)NODES_MAX * NCLS];
__device__ float g_w1t[(long long)HID * IN_F];       // W1^T, tf32-pre-rounded

// ---------------- PTX helpers (baseline sm_80+ ISA only) -----------------
__device__ __forceinline__ unsigned smem_u32(const void* p) {
    unsigned a;
    asm("{ .reg .u64 t; cvta.to.shared.u64 t, %1; cvt.u32.u64 %0, t; }"
        : "=r"(a) : "l"(p));
    return a;
}
__device__ __forceinline__ unsigned lds32(unsigned addr) {
    unsigned v;
    asm volatile("ld.shared.b32 %0, [%1];" : "=r"(v) : "r"(addr));
    return v;
}
__device__ __forceinline__ unsigned tf32r(unsigned v) {
    unsigned r;
    asm("cvt.rna.tf32.f32 %0, %1;" : "=r"(r) : "r"(v));
    return r;
}
__device__ __forceinline__ void mma_tf32(float* c, const unsigned* a, const unsigned* b) {
    asm volatile(
        "mma.sync.aligned.m16n8k8.row.col.f32.tf32.tf32.f32 "
        "{%0,%1,%2,%3}, {%4,%5,%6,%7}, {%8,%9}, {%0,%1,%2,%3};"
        : "+f"(c[0]), "+f"(c[1]), "+f"(c[2]), "+f"(c[3])
        : "r"(a[0]), "r"(a[1]), "r"(a[2]), "r"(a[3]), "r"(b[0]), "r"(b[1]));
}
__device__ __forceinline__ void cpasync16(unsigned dst, const void* src, int ok) {
    int sz = ok ? 16 : 0;
    asm volatile("cp.async.cg.shared.global [%0], [%1], 16, %2;"
                 :: "r"(dst), "l"(src), "r"(sz) : "memory");
}
#define CP_COMMIT()  asm volatile("cp.async.commit_group;" ::: "memory")
#define CP_WAIT1()   asm volatile("cp.async.wait_group 1;" ::: "memory")

// ---------------- edge dtype detection ----------------------------------
__global__ void k_detect(const int* __restrict__ ei, int E) {
    __shared__ int s_any;
    if (threadIdx.x == 0) s_any = 0;
    __syncthreads();
    int m = E < 2048 ? E : 2048;
    int nz = 0;
    for (int i = threadIdx.x; i < m; i += blockDim.x) nz |= ei[2 * i + 1];
    if (nz) s_any = 1;
    __syncthreads();
    if (threadIdx.x == 0) g_shift = (s_any == 0) ? 1 : 0;
}
__global__ void k_zero(int n) {
    int i = blockIdx.x * blockDim.x + threadIdx.x;
    if (i < n) g_deg[i] = 0;
}
__global__ void k_count(const int* __restrict__ ei, int E) {
    int e = blockIdx.x * blockDim.x + threadIdx.x;
    if (e < E) {
        int sh = g_shift;
        int d = ei[(E + e) << sh];
        atomicAdd(&g_deg[d], 1);
    }
}
__global__ void k_dinv(int n) {
    int i = blockIdx.x * blockDim.x + threadIdx.x;
    if (i < n) g_dinv[i] = 1.0f / sqrtf((float)(g_deg[i] + 1));
}
__global__ void k_scan(int n) {
    __shared__ int s[1024];
    __shared__ int carry_s;
    int tid = threadIdx.x;
    if (tid == 0) carry_s = 0;
    __syncthreads();
    for (int base = 0; base < n; base += 1024) {
        int i = base + tid;
        int v = (i < n) ? g_deg[i] : 0;
        s[tid] = v;
        __syncthreads();
        for (int off = 1; off < 1024; off <<= 1) {
            int t = (tid >= off) ? s[tid - off] : 0;
            __syncthreads();
            s[tid] += t;
            __syncthreads();
        }
        int carry = carry_s;
        __syncthreads();
        if (tid == 1023) carry_s = carry + s[1023];
        if (i < n) {
            int excl = carry + s[tid] - v;
            g_rowptr[i] = excl;
            g_cursor[i] = excl;
        }
        __syncthreads();
    }
    if (tid == 0) g_rowptr[n] = carry_s;
}
__global__ void k_fill(const int* __restrict__ ei, int E) {
    int e = blockIdx.x * blockDim.x + threadIdx.x;
    if (e < E) {
        int sh = g_shift;
        int s = ei[e << sh];
        int d = ei[(E + e) << sh];
        int pos = atomicAdd(&g_cursor[d], 1);
        g_col[pos] = s;
    }
}

// ---------------- W1 transpose + tf32 pre-round --------------------------
__global__ void k_convW(const float* __restrict__ W1) {
    int idx = blockIdx.x * blockDim.x + threadIdx.x;
    if (idx >= IN_F * HID) return;
    int k = idx / HID, n = idx % HID;       // coalesced read of W1[k][n]
    unsigned t = tf32r(__float_as_uint(W1[idx]));
    g_w1t[(long long)n * IN_F + k] = __uint_as_float(t);
}

// ---------------- GEMM1 via mma.sync tf32 single-pass --------------------
// CTA tile M=128 x N=128, BK=64, 256 threads (8 warps, warp tile 32x64),
// fp32 SMEM tiles, XOR swizzle (16B chunk ^ row&15), cp.async double buffer.
#define TB_OFF 32768
#define STAGE_BYTES 65536
#define GSMEM_TOTAL (2 * STAGE_BYTES)

__device__ __forceinline__ void load_stage(unsigned base, const float* __restrict__ x,
                                           int kt, int m0, int n0, int M, int tid) {
    int k0 = kt * 64;
#pragma unroll
    for (int it = 0; it < 8; it++) {
        int ch = tid + it * 256;            // 2048 chunks: A tile
        int r = ch >> 4, seg = ch & 15;
        unsigned so = (unsigned)(r * 256 + ((seg ^ (r & 15)) << 4));
        int gr = m0 + r;
        cpasync16(base + so, &x[(long long)gr * IN_F + k0 + seg * 4], gr < M);
    }
#pragma unroll
    for (int it = 0; it < 8; it++) {
        int ch = tid + it * 256;            // 2048 chunks: B tile
        int r = ch >> 4, seg = ch & 15;
        unsigned so = (unsigned)(r * 256 + ((seg ^ (r & 15)) << 4));
        cpasync16(base + TB_OFF + so,
                  &g_w1t[(long long)(n0 + r) * IN_F + k0 + seg * 4], 1);
    }
}

__global__ __launch_bounds__(256, 1)
void k_gemm1_tf32(const float* __restrict__ x, int M) {
    extern __shared__ __align__(128) char sm[];
    unsigned sb = smem_u32(sm);
    int tid = threadIdx.x, wid = tid >> 5, lane = tid & 31;
    int m0 = blockIdx.y * 128, n0 = blockIdx.x * 128;
    int wm = (wid >> 1) * 32;        // warp m-offset (0,32,64,96)
    int wn = (wid & 1) * 64;         // warp n-offset (0,64)
    int gID = lane >> 2, tig = lane & 3;

    float acc[2][8][4];
#pragma unroll
    for (int i = 0; i < 2; i++)
#pragma unroll
        for (int j = 0; j < 8; j++)
#pragma unroll
            for (int q = 0; q < 4; q++) acc[i][j][q] = 0.f;

    load_stage(sb, x, 0, m0, n0, M, tid);
    CP_COMMIT();

    for (int kt = 0; kt < NK64; kt++) {
        unsigned cur = sb + (kt & 1) * STAGE_BYTES;
        if (kt + 1 < NK64)
            load_stage(sb + ((kt + 1) & 1) * STAGE_BYTES, x, kt + 1, m0, n0, M, tid);
        CP_COMMIT();
        CP_WAIT1();
        __syncthreads();

#pragma unroll
        for (int ks = 0; ks < 8; ks++) {
            unsigned c0 = 2 * ks, c1 = 2 * ks + 1;   // 16B-chunk indices
            unsigned a[2][4];
#pragma unroll
            for (int mf = 0; mf < 2; mf++) {
                unsigned r0 = (unsigned)(wm + mf * 16 + gID);
                unsigned r1 = r0 + 8;
                unsigned b0 = cur + r0 * 256 + tig * 4;
                unsigned b1 = cur + r1 * 256 + tig * 4;
                a[mf][0] = tf32r(lds32(b0 + ((c0 ^ (r0 & 15)) << 4)));
                a[mf][1] = tf32r(lds32(b1 + ((c0 ^ (r1 & 15)) << 4)));
                a[mf][2] = tf32r(lds32(b0 + ((c1 ^ (r0 & 15)) << 4)));
                a[mf][3] = tf32r(lds32(b1 + ((c1 ^ (r1 & 15)) << 4)));
            }
#pragma unroll
            for (int nf = 0; nf < 8; nf++) {
                unsigned nr = (unsigned)(wn + nf * 8 + gID);
                unsigned bb = cur + TB_OFF + nr * 256 + tig * 4;
                unsigned b[2];
                b[0] = lds32(bb + ((c0 ^ (nr & 15)) << 4));
                b[1] = lds32(bb + ((c1 ^ (nr & 15)) << 4));
                mma_tf32(acc[0][nf], a[0], b);
                mma_tf32(acc[1][nf], a[1], b);
            }
        }
        __syncthreads();
    }

    // epilogue: direct STG.64 of accumulators
#pragma unroll
    for (int mf = 0; mf < 2; mf++) {
        int r0 = m0 + wm + mf * 16 + gID;
#pragma unroll
        for (int nf = 0; nf < 8; nf++) {
            int col = n0 + wn + nf * 8 + tig * 2;
            if (r0 < M)
                *(float2*)&g_h1[(long long)r0 * HID + col] =
                    make_float2(acc[mf][nf][0], acc[mf][nf][1]);
            if (r0 + 8 < M)
                *(float2*)&g_h1[(long long)(r0 + 8) * HID + col] =
                    make_float2(acc[mf][nf][2], acc[mf][nf][3]);
        }
    }
}

// ---------------- SpMM1: r1 = relu( dinv_d * (sum dinv_s h1[s]) + b1 ) ---
__global__ void k_spmm1(const float* __restrict__ b1) {
    int row = blockIdx.x;
    int c = threadIdx.x << 2;
    float di = g_dinv[row];

    float4 v = *(const float4*)&g_h1[(long long)row * HID + c];
    float4 acc;
    acc.x = di * v.x; acc.y = di * v.y; acc.z = di * v.z; acc.w = di * v.w;

    int p0 = g_rowptr[row], p1 = g_rowptr[row + 1];
    for (int p = p0; p < p1; ++p) {
        int s = g_col[p];
        float w = g_dinv[s];
        float4 u = *(const float4*)&g_h1[(long long)s * HID + c];
        acc.x += w * u.x; acc.y += w * u.y; acc.z += w * u.z; acc.w += w * u.w;
    }
    float4 bb = *(const float4*)&b1[c];
    acc.x = fmaxf(acc.x * di + bb.x, 0.f);
    acc.y = fmaxf(acc.y * di + bb.y, 0.f);
    acc.z = fmaxf(acc.z * di + bb.z, 0.f);
    acc.w = fmaxf(acc.w * di + bb.w, 0.f);
    *(float4*)&g_r1[(long long)row * HID + c] = acc;
}

// ---------------- GEMM2: h2 = r1 @ W2  (M x 512 @ 512 x 10) -------------
__global__ void k_gemm2(const float* __restrict__ W2, int Nn) {
    __shared__ float w[HID * NCLS];
    for (int i = threadIdx.x; i < HID * NCLS; i += blockDim.x) w[i] = W2[i];
    __syncthreads();
    int row = blockIdx.x * blockDim.x + threadIdx.x;
    if (row >= Nn) return;
    float acc[NCLS];
#pragma unroll
    for (int j = 0; j < NCLS; j++) acc[j] = 0.f;
    const float4* xr = (const float4*)&g_r1[(long long)row * HID];
#pragma unroll 4
    for (int k4 = 0; k4 < HID / 4; k4++) {
        float4 x = xr[k4];
        const float* w0 = &w[(k4 * 4) * NCLS];
#pragma unroll
        for (int j = 0; j < NCLS; j++)
            acc[j] += x.x * w0[j] + x.y * w0[NCLS + j] +
                      x.z * w0[2 * NCLS + j] + x.w * w0[3 * NCLS + j];
    }
#pragma unroll
    for (int j = 0; j < NCLS; j++) g_h2[(long long)row * NCLS + j] = acc[j];
}

// ---------------- SpMM2 + bias + log_softmax (warp per row) -------------
__global__ void k_spmm2(const float* __restrict__ b2, float* __restrict__ out, int Nn) {
    int row = (blockIdx.x * blockDim.x + threadIdx.x) >> 5;
    int lane = threadIdx.x & 31;
    if (row >= Nn) return;

    float di = g_dinv[row];
    float acc = 0.f;
    if (lane < NCLS) acc = di * g_h2[(long long)row * NCLS + lane];

    int p0 = g_rowptr[row], p1 = g_rowptr[row + 1];
    for (int p = p0; p < p1; ++p) {
        int s = g_col[p];
        float w = g_dinv[s];
        if (lane < NCLS) acc += w * g_h2[(long long)s * NCLS + lane];
    }
    acc = acc * di + ((lane < NCLS) ? b2[lane] : 0.f);

    float v = (lane < NCLS) ? acc : -3.4e38f;
#pragma unroll
    for (int o = 16; o > 0; o >>= 1) v = fmaxf(v, __shfl_xor_sync(0xffffffffu, v, o));
    float ex = (lane < NCLS) ? expf(acc - v) : 0.f;
#pragma unroll
    for (int o = 16; o > 0; o >>= 1) ex += __shfl_xor_sync(0xffffffffu, ex, o);
    float lse = logf(ex);
    if (lane < NCLS) out[(long long)row * NCLS + lane] = acc - v - lse;
}

// ---------------- launch ---------------------------------------------------
extern "C" void kernel_launch(void* const* d_in, const int* in_sizes, int n_in,
                              void* d_out, int out_size) {
    const float* x  = (const float*)d_in[0];
    const int*   ei = (const int*)d_in[1];
    const float* W1 = (const float*)d_in[2];
    const float* b1 = (const float*)d_in[3];
    const float* W2 = (const float*)d_in[4];
    const float* b2 = (const float*)d_in[5];
    float* out = (float*)d_out;

    int Nn = in_sizes[0] / IN_F;          // 20000
    int E  = in_sizes[1] / 2;

    k_detect<<<1, 256>>>(ei, E);
    k_zero  <<<(Nn + 255) / 256, 256>>>(Nn);
    k_count <<<(E + 255) / 256, 256>>>(ei, E);
    k_dinv  <<<(Nn + 255) / 256, 256>>>(Nn);
    k_scan  <<<1, 1024>>>(Nn);
    k_fill  <<<(E + 255) / 256, 256>>>(ei, E);

    k_convW<<<(IN_F * HID + 255) / 256, 256>>>(W1);

    cudaFuncSetAttribute(k_gemm1_tf32, cudaFuncAttributeMaxDynamicSharedMemorySize,
                         GSMEM_TOTAL);
    dim3 g1(HID / 128, (Nn + 127) / 128);   // (4, 157)
    k_gemm1_tf32<<<g1, 256, GSMEM_TOTAL>>>(x, Nn);

    k_spmm1 <<<Nn, 128>>>(b1);
    k_gemm2 <<<(Nn + 127) / 128, 128>>>(W2, Nn);
    k_spmm2 <<<(Nn * 32 + 127) / 128, 128>>>(b2, out, Nn);
}

// round 10
// speedup vs baseline: 2.7126x; 1.0289x over previous
#include <cuda_runtime.h>
#include <cuda_bf16.h>
#include <math.h>

// Problem constants
#define IN_F   4096
#define HID    512
#define NCLS   10
#define NODES_MAX 20000
#define MAX_E  700000
#define NK64   (IN_F / 64)          // 64 K-stages of 64

// ---------------- device scratch (no allocation allowed) ----------------
__device__ int   g_shift;
__device__ int   g_deg[NODES_MAX];
__device__ float g_dinv[NODES_MAX];
__device__ int   g_rowptr[NODES_MAX + 1];
__device__ int   g_cursor[NODES_MAX];
__device__ int   g_col[MAX_E];
__device__ float g_h1[(long long)NODES_MAX * HID];   // conv1 dense result
__device__ float g_r1[(long long)NODES_MAX * HID];   // relu(A_hat h1 + b1)
__device__ float g_h2[(long long)NODES_MAX * NCLS];
__device__ float g_w1t[(long long)HID * IN_F];       // W1^T, tf32-pre-rounded

// ---------------- PTX helpers (baseline sm_80+ ISA only) -----------------
__device__ __forceinline__ unsigned smem_u32(const void* p) {
    unsigned a;
    asm("{ .reg .u64 t; cvta.to.shared.u64 t, %1; cvt.u32.u64 %0, t; }"
        : "=r"(a) : "l"(p));
    return a;
}
__device__ __forceinline__ void ldsm4(unsigned* r, unsigned addr) {
    asm volatile("ldmatrix.sync.aligned.m8n8.x4.shared.b16 {%0,%1,%2,%3}, [%4];"
                 : "=r"(r[0]), "=r"(r[1]), "=r"(r[2]), "=r"(r[3]) : "r"(addr));
}
__device__ __forceinline__ unsigned tf32r(unsigned v) {
    unsigned r;
    asm("cvt.rna.tf32.f32 %0, %1;" : "=r"(r) : "r"(v));
    return r;
}
__device__ __forceinline__ void mma_tf32(float* c, const unsigned* a, const unsigned* b) {
    asm volatile(
        "mma.sync.aligned.m16n8k8.row.col.f32.tf32.tf32.f32 "
        "{%0,%1,%2,%3}, {%4,%5,%6,%7}, {%8,%9}, {%0,%1,%2,%3};"
        : "+f"(c[0]), "+f"(c[1]), "+f"(c[2]), "+f"(c[3])
        : "r"(a[0]), "r"(a[1]), "r"(a[2]), "r"(a[3]), "r"(b[0]), "r"(b[1]));
}
__device__ __forceinline__ void cpasync16(unsigned dst, const void* src, int ok) {
    int sz = ok ? 16 : 0;
    asm volatile("cp.async.cg.shared.global [%0], [%1], 16, %2;"
                 :: "r"(dst), "l"(src), "r"(sz) : "memory");
}
#define CP_COMMIT()  asm volatile("cp.async.commit_group;" ::: "memory")
#define CP_WAIT2()   asm volatile("cp.async.wait_group 2;" ::: "memory")

// ---------------- edge dtype detection ----------------------------------
__global__ void k_detect(const int* __restrict__ ei, int E) {
    __shared__ int s_any;
    if (threadIdx.x == 0) s_any = 0;
    __syncthreads();
    int m = E < 2048 ? E : 2048;
    int nz = 0;
    for (int i = threadIdx.x; i < m; i += blockDim.x) nz |= ei[2 * i + 1];
    if (nz) s_any = 1;
    __syncthreads();
    if (threadIdx.x == 0) g_shift = (s_any == 0) ? 1 : 0;
}
__global__ void k_zero(int n) {
    int i = blockIdx.x * blockDim.x + threadIdx.x;
    if (i < n) g_deg[i] = 0;
}
__global__ void k_count(const int* __restrict__ ei, int E) {
    int e = blockIdx.x * blockDim.x + threadIdx.x;
    if (e < E) {
        int sh = g_shift;
        int d = ei[(E + e) << sh];
        atomicAdd(&g_deg[d], 1);
    }
}
__global__ void k_dinv(int n) {
    int i = blockIdx.x * blockDim.x + threadIdx.x;
    if (i < n) g_dinv[i] = 1.0f / sqrtf((float)(g_deg[i] + 1));
}
__global__ void k_scan(int n) {
    __shared__ int s[1024];
    __shared__ int carry_s;
    int tid = threadIdx.x;
    if (tid == 0) carry_s = 0;
    __syncthreads();
    for (int base = 0; base < n; base += 1024) {
        int i = base + tid;
        int v = (i < n) ? g_deg[i] : 0;
        s[tid] = v;
        __syncthreads();
        for (int off = 1; off < 1024; off <<= 1) {
            int t = (tid >= off) ? s[tid - off] : 0;
            __syncthreads();
            s[tid] += t;
            __syncthreads();
        }
        int carry = carry_s;
        __syncthreads();
        if (tid == 1023) carry_s = carry + s[1023];
        if (i < n) {
            int excl = carry + s[tid] - v;
            g_rowptr[i] = excl;
            g_cursor[i] = excl;
        }
        __syncthreads();
    }
    if (tid == 0) g_rowptr[n] = carry_s;
}
__global__ void k_fill(const int* __restrict__ ei, int E) {
    int e = blockIdx.x * blockDim.x + threadIdx.x;
    if (e < E) {
        int sh = g_shift;
        int s = ei[e << sh];
        int d = ei[(E + e) << sh];
        int pos = atomicAdd(&g_cursor[d], 1);
        g_col[pos] = s;
    }
}

// ---------------- W1 transpose + tf32 pre-round --------------------------
__global__ void k_convW(const float* __restrict__ W1) {
    int idx = blockIdx.x * blockDim.x + threadIdx.x;
    if (idx >= IN_F * HID) return;
    int k = idx / HID, n = idx % HID;       // coalesced read of W1[k][n]
    unsigned t = tf32r(__float_as_uint(W1[idx]));
    g_w1t[(long long)n * IN_F + k] = __uint_as_float(t);
}

// ---------------- GEMM1 via mma.sync tf32 + ldmatrix ---------------------
// CTA tile M=128 x N=128, BK=64, 256 threads (8 warps, warp tile 32x64),
// fp32 SMEM tiles, XOR swizzle (16B chunk ^ row&15), cp.async 3-stage.
#define TB_OFF 32768
#define STAGE_BYTES 65536
#define GSMEM_TOTAL (3 * STAGE_BYTES)

__device__ __forceinline__ void load_stage(unsigned base, const float* __restrict__ x,
                                           int kt, int m0, int n0, int M, int tid) {
    int k0 = kt * 64;
#pragma unroll
    for (int it = 0; it < 8; it++) {
        int ch = tid + it * 256;            // 2048 chunks: A tile
        int r = ch >> 4, seg = ch & 15;
        unsigned so = (unsigned)(r * 256 + ((seg ^ (r & 15)) << 4));
        int gr = m0 + r;
        cpasync16(base + so, &x[(long long)gr * IN_F + k0 + seg * 4], gr < M);
    }
#pragma unroll
    for (int it = 0; it < 8; it++) {
        int ch = tid + it * 256;            // 2048 chunks: B tile
        int r = ch >> 4, seg = ch & 15;
        unsigned so = (unsigned)(r * 256 + ((seg ^ (r & 15)) << 4));
        cpasync16(base + TB_OFF + so,
                  &g_w1t[(long long)(n0 + r) * IN_F + k0 + seg * 4], 1);
    }
}

__global__ __launch_bounds__(256, 1)
void k_gemm1_tf32(const float* __restrict__ x, int M) {
    extern __shared__ __align__(128) char sm[];
    unsigned sb = smem_u32(sm);
    int tid = threadIdx.x, wid = tid >> 5, lane = tid & 31;
    int m0 = blockIdx.y * 128, n0 = blockIdx.x * 128;
    int wm = (wid >> 1) * 32;        // warp m-offset (0,32,64,96)
    int wn = (wid & 1) * 64;         // warp n-offset (0,64)
    int gID = lane >> 2, tig = lane & 3;

    float acc[2][8][4];
#pragma unroll
    for (int i = 0; i < 2; i++)
#pragma unroll
        for (int j = 0; j < 8; j++)
#pragma unroll
            for (int q = 0; q < 4; q++) acc[i][j][q] = 0.f;

    // ---- ldmatrix lane addressing (tile-local) ----
    // A tile (per mf): matrices {rows0-7,c_lo},{rows8-15,c_lo},{rows0-7,c_hi},{rows8-15,c_hi}
    int mtx = lane >> 3, rin = lane & 7;
    unsigned paA = (unsigned)(mtx >> 1);            // chunk parity for this lane
    unsigned aRow0 = (unsigned)(wm + ((mtx & 1) << 3) + rin);        // mf=0
    unsigned aRow1 = aRow0 + 16;                                     // mf=1
    unsigned aBase0 = aRow0 * 256, aMask0 = aRow0 & 15;
    unsigned aBase1 = aRow1 * 256, aMask1 = aRow1 & 15;
    // B tile (per nf-pair p): matrices {nf=2p,c_lo},{nf=2p,c_hi},{nf=2p+1,c_lo},{nf=2p+1,c_hi}
    unsigned pbB = (unsigned)(mtx & 1);
    unsigned bRowBase = (unsigned)(wn + ((mtx >> 1) << 3) + rin);    // p=0 n-row
    unsigned bBase[4], bMask[4];
#pragma unroll
    for (int p = 0; p < 4; p++) {
        unsigned nr = bRowBase + p * 16;
        bBase[p] = nr * 256;
        bMask[p] = nr & 15;
    }

    load_stage(sb, x, 0, m0, n0, M, tid);
    CP_COMMIT();
    load_stage(sb + STAGE_BYTES, x, 1, m0, n0, M, tid);
    CP_COMMIT();

    int buf = 0;
    for (int kt = 0; kt < NK64; kt++) {
        unsigned cur = sb + buf * STAGE_BYTES;
        int nb = buf + 2; if (nb >= 3) nb -= 3;
        if (kt + 2 < NK64)
            load_stage(sb + nb * STAGE_BYTES, x, kt + 2, m0, n0, M, tid);
        CP_COMMIT();
        CP_WAIT2();
        __syncthreads();

#pragma unroll
        for (int ks = 0; ks < 8; ks++) {
            unsigned cA = 2 * ks + paA;
            unsigned cB = 2 * ks + pbB;
            unsigned a[2][4];
            ldsm4(a[0], cur + aBase0 + ((cA ^ aMask0) << 4));
            ldsm4(a[1], cur + aBase1 + ((cA ^ aMask1) << 4));
#pragma unroll
            for (int q = 0; q < 4; q++) {
                a[0][q] = tf32r(a[0][q]);
                a[1][q] = tf32r(a[1][q]);
            }
#pragma unroll
            for (int p = 0; p < 4; p++) {
                unsigned b[4];
                ldsm4(b, cur + TB_OFF + bBase[p] + ((cB ^ bMask[p]) << 4));
                mma_tf32(acc[0][2 * p],     a[0], b);
                mma_tf32(acc[0][2 * p + 1], a[0], b + 2);
                mma_tf32(acc[1][2 * p],     a[1], b);
                mma_tf32(acc[1][2 * p + 1], a[1], b + 2);
            }
        }
        __syncthreads();
        buf++; if (buf == 3) buf = 0;
    }

    // epilogue: direct STG.64 of accumulators
#pragma unroll
    for (int mf = 0; mf < 2; mf++) {
        int r0 = m0 + wm + mf * 16 + gID;
#pragma unroll
        for (int nf = 0; nf < 8; nf++) {
            int col = n0 + wn + nf * 8 + tig * 2;
            if (r0 < M)
                *(float2*)&g_h1[(long long)r0 * HID + col] =
                    make_float2(acc[mf][nf][0], acc[mf][nf][1]);
            if (r0 + 8 < M)
                *(float2*)&g_h1[(long long)(r0 + 8) * HID + col] =
                    make_float2(acc[mf][nf][2], acc[mf][nf][3]);
        }
    }
}

// ---------------- SpMM1: r1 = relu( dinv_d * (sum dinv_s h1[s]) + b1 ) ---
__global__ void k_spmm1(const float* __restrict__ b1) {
    int row = blockIdx.x;
    int c = threadIdx.x << 2;
    float di = g_dinv[row];

    float4 v = *(const float4*)&g_h1[(long long)row * HID + c];
    float4 acc;
    acc.x = di * v.x; acc.y = di * v.y; acc.z = di * v.z; acc.w = di * v.w;

    int p0 = g_rowptr[row], p1 = g_rowptr[row + 1];
    for (int p = p0; p < p1; ++p) {
        int s = g_col[p];
        float w = g_dinv[s];
        float4 u = *(const float4*)&g_h1[(long long)s * HID + c];
        acc.x += w * u.x; acc.y += w * u.y; acc.z += w * u.z; acc.w += w * u.w;
    }
    float4 bb = *(const float4*)&b1[c];
    acc.x = fmaxf(acc.x * di + bb.x, 0.f);
    acc.y = fmaxf(acc.y * di + bb.y, 0.f);
    acc.z = fmaxf(acc.z * di + bb.z, 0.f);
    acc.w = fmaxf(acc.w * di + bb.w, 0.f);
    *(float4*)&g_r1[(long long)row * HID + c] = acc;
}

// ---------------- GEMM2: h2 = r1 @ W2  (M x 512 @ 512 x 10) -------------
__global__ void k_gemm2(const float* __restrict__ W2, int Nn) {
    __shared__ float w[HID * NCLS];
    for (int i = threadIdx.x; i < HID * NCLS; i += blockDim.x) w[i] = W2[i];
    __syncthreads();
    int row = blockIdx.x * blockDim.x + threadIdx.x;
    if (row >= Nn) return;
    float acc[NCLS];
#pragma unroll
    for (int j = 0; j < NCLS; j++) acc[j] = 0.f;
    const float4* xr = (const float4*)&g_r1[(long long)row * HID];
#pragma unroll 4
    for (int k4 = 0; k4 < HID / 4; k4++) {
        float4 x = xr[k4];
        const float* w0 = &w[(k4 * 4) * NCLS];
#pragma unroll
        for (int j = 0; j < NCLS; j++)
            acc[j] += x.x * w0[j] + x.y * w0[NCLS + j] +
                      x.z * w0[2 * NCLS + j] + x.w * w0[3 * NCLS + j];
    }
#pragma unroll
    for (int j = 0; j < NCLS; j++) g_h2[(long long)row * NCLS + j] = acc[j];
}

// ---------------- SpMM2 + bias + log_softmax (warp per row) -------------
__global__ void k_spmm2(const float* __restrict__ b2, float* __restrict__ out, int Nn) {
    int row = (blockIdx.x * blockDim.x + threadIdx.x) >> 5;
    int lane = threadIdx.x & 31;
    if (row >= Nn) return;

    float di = g_dinv[row];
    float acc = 0.f;
    if (lane < NCLS) acc = di * g_h2[(long long)row * NCLS + lane];

    int p0 = g_rowptr[row], p1 = g_rowptr[row + 1];
    for (int p = p0; p < p1; ++p) {
        int s = g_col[p];
        float w = g_dinv[s];
        if (lane < NCLS) acc += w * g_h2[(long long)s * NCLS + lane];
    }
    acc = acc * di + ((lane < NCLS) ? b2[lane] : 0.f);

    float v = (lane < NCLS) ? acc : -3.4e38f;
#pragma unroll
    for (int o = 16; o > 0; o >>= 1) v = fmaxf(v, __shfl_xor_sync(0xffffffffu, v, o));
    float ex = (lane < NCLS) ? expf(acc - v) : 0.f;
#pragma unroll
    for (int o = 16; o > 0; o >>= 1) ex += __shfl_xor_sync(0xffffffffu, ex, o);
    float lse = logf(ex);
    if (lane < NCLS) out[(long long)row * NCLS + lane] = acc - v - lse;
}

// ---------------- launch ---------------------------------------------------
extern "C" void kernel_launch(void* const* d_in, const int* in_sizes, int n_in,
                              void* d_out, int out_size) {
    const float* x  = (const float*)d_in[0];
    const int*   ei = (const int*)d_in[1];
    const float* W1 = (const float*)d_in[2];
    const float* b1 = (const float*)d_in[3];
    const float* W2 = (const float*)d_in[4];
    const float* b2 = (const float*)d_in[5];
    float* out = (float*)d_out;

    int Nn = in_sizes[0] / IN_F;          // 20000
    int E  = in_sizes[1] / 2;

    k_detect<<<1, 256>>>(ei, E);
    k_zero  <<<(Nn + 255) / 256, 256>>>(Nn);
    k_count <<<(E + 255) / 256, 256>>>(ei, E);
    k_dinv  <<<(Nn + 255) / 256, 256>>>(Nn);
    k_scan  <<<1, 1024>>>(Nn);
    k_fill  <<<(E + 255) / 256, 256>>>(ei, E);

    k_convW<<<(IN_F * HID + 255) / 256, 256>>>(W1);

    cudaFuncSetAttribute(k_gemm1_tf32, cudaFuncAttributeMaxDynamicSharedMemorySize,
                         GSMEM_TOTAL);
    dim3 g1(HID / 128, (Nn + 127) / 128);   // (4, 157)
    k_gemm1_tf32<<<g1, 256, GSMEM_TOTAL>>>(x, Nn);

    k_spmm1 <<<Nn, 128>>>(b1);
    k_gemm2 <<<(Nn + 127) / 128, 128>>>(W2, Nn);
    k_spmm2 <<<(Nn * 32 + 127) / 128, 128>>>(b2, out, Nn);
}

// round 13
// speedup vs baseline: 4.0575x; 1.4958x over previous
#include <cuda_runtime.h>
#include <cuda_bf16.h>
#include <math.h>

// Problem constants
#define IN_F   4096
#define HID    512
#define NCLS   10
#define NODES_MAX 20000
#define MAX_E  700000
#define NK64   (IN_F / 64)          // 64 K-stages of 64

// ---------------- device scratch (no allocation allowed) ----------------
__device__ int   g_shift;
__device__ int   g_deg[NODES_MAX];
__device__ float g_dinv[NODES_MAX];
__device__ int   g_rowptr[NODES_MAX + 1];
__device__ int   g_cursor[NODES_MAX];
__device__ int   g_col[MAX_E];
__device__ float g_h1[(long long)NODES_MAX * HID];   // conv1 dense result
__device__ float g_r1[(long long)NODES_MAX * HID];   // relu(A_hat h1 + b1)
__device__ float g_h2[(long long)NODES_MAX * NCLS];
__device__ __nv_bfloat16 g_xbf[(long long)NODES_MAX * IN_F];   // x as bf16
__device__ __nv_bfloat16 g_w1b[(long long)HID * IN_F];         // W1^T bf16 [n][k]

// ---------------- PTX helpers (baseline sm_80+ ISA only) -----------------
__device__ __forceinline__ unsigned smem_u32(const void* p) {
    unsigned a;
    asm("{ .reg .u64 t; cvta.to.shared.u64 t, %1; cvt.u32.u64 %0, t; }"
        : "=r"(a) : "l"(p));
    return a;
}
__device__ __forceinline__ void ldsm4(unsigned* r, unsigned addr) {
    asm volatile("ldmatrix.sync.aligned.m8n8.x4.shared.b16 {%0,%1,%2,%3}, [%4];"
                 : "=r"(r[0]), "=r"(r[1]), "=r"(r[2]), "=r"(r[3]) : "r"(addr));
}
__device__ __forceinline__ void mma16816(float* c, const unsigned* a, const unsigned* b) {
    asm volatile(
        "mma.sync.aligned.m16n8k16.row.col.f32.bf16.bf16.f32 "
        "{%0,%1,%2,%3}, {%4,%5,%6,%7}, {%8,%9}, {%0,%1,%2,%3};"
        : "+f"(c[0]), "+f"(c[1]), "+f"(c[2]), "+f"(c[3])
        : "r"(a[0]), "r"(a[1]), "r"(a[2]), "r"(a[3]), "r"(b[0]), "r"(b[1]));
}
__device__ __forceinline__ void cpasync16(unsigned dst, const void* src, int ok) {
    int sz = ok ? 16 : 0;
    asm volatile("cp.async.cg.shared.global [%0], [%1], 16, %2;"
                 :: "r"(dst), "l"(src), "r"(sz) : "memory");
}
#define CP_COMMIT()  asm volatile("cp.async.commit_group;" ::: "memory")
#define CP_WAIT2()   asm volatile("cp.async.wait_group 2;" ::: "memory")
#define SW(o) ((o) ^ (((o) >> 3) & 0x70))

// ---------------- edge dtype detection ----------------------------------
__global__ void k_detect(const int* __restrict__ ei, int E) {
    __shared__ int s_any;
    if (threadIdx.x == 0) s_any = 0;
    __syncthreads();
    int m = E < 2048 ? E : 2048;
    int nz = 0;
    for (int i = threadIdx.x; i < m; i += blockDim.x) nz |= ei[2 * i + 1];
    if (nz) s_any = 1;
    __syncthreads();
    if (threadIdx.x == 0) g_shift = (s_any == 0) ? 1 : 0;
}
__global__ void k_zero(int n) {
    int i = blockIdx.x * blockDim.x + threadIdx.x;
    if (i < n) g_deg[i] = 0;
}
__global__ void k_count(const int* __restrict__ ei, int E) {
    int e = blockIdx.x * blockDim.x + threadIdx.x;
    if (e < E) {
        int sh = g_shift;
        int d = ei[(E + e) << sh];
        atomicAdd(&g_deg[d], 1);
    }
}
__global__ void k_dinv(int n) {
    int i = blockIdx.x * blockDim.x + threadIdx.x;
    if (i < n) g_dinv[i] = 1.0f / sqrtf((float)(g_deg[i] + 1));
}
__global__ void k_scan(int n) {
    __shared__ int s[1024];
    __shared__ int carry_s;
    int tid = threadIdx.x;
    if (tid == 0) carry_s = 0;
    __syncthreads();
    for (int base = 0; base < n; base += 1024) {
        int i = base + tid;
        int v = (i < n) ? g_deg[i] : 0;
        s[tid] = v;
        __syncthreads();
        for (int off = 1; off < 1024; off <<= 1) {
            int t = (tid >= off) ? s[tid - off] : 0;
            __syncthreads();
            s[tid] += t;
            __syncthreads();
        }
        int carry = carry_s;
        __syncthreads();
        if (tid == 1023) carry_s = carry + s[1023];
        if (i < n) {
            int excl = carry + s[tid] - v;
            g_rowptr[i] = excl;
            g_cursor[i] = excl;
        }
        __syncthreads();
    }
    if (tid == 0) g_rowptr[n] = carry_s;
}
__global__ void k_fill(const int* __restrict__ ei, int E) {
    int e = blockIdx.x * blockDim.x + threadIdx.x;
    if (e < E) {
        int sh = g_shift;
        int s = ei[e << sh];
        int d = ei[(E + e) << sh];
        int pos = atomicAdd(&g_cursor[d], 1);
        g_col[pos] = s;
    }
}

// ---------------- bf16 conversions ---------------------------------------
__global__ void k_convA(const float* __restrict__ x, long long total4) {
    long long i = (long long)blockIdx.x * blockDim.x + threadIdx.x;
    if (i >= total4) return;
    float4 v = ((const float4*)x)[i];
    __nv_bfloat162 a = {__float2bfloat16(v.x), __float2bfloat16(v.y)};
    __nv_bfloat162 b = {__float2bfloat16(v.z), __float2bfloat16(v.w)};
    uint2 u;
    u.x = *(unsigned*)&a; u.y = *(unsigned*)&b;
    *(uint2*)&g_xbf[4 * i] = u;
}
__global__ void k_convW(const float* __restrict__ W1) {
    int idx = blockIdx.x * blockDim.x + threadIdx.x;
    if (idx >= IN_F * HID) return;
    int k = idx / HID, n = idx % HID;       // coalesced read of W1[k][n]
    g_w1b[(long long)n * IN_F + k] = __float2bfloat16(W1[idx]);
}

// ---------------- GEMM1 via mma.sync bf16 single-pass --------------------
// CTA tile M=128 x N=128, BK=64, 256 threads (8 warps, warp tile 32x64),
// SW128-swizzled bf16 SMEM, ldmatrix.x4 frags, cp.async 3-stage pipeline.
#define TB_OFF 16384
#define STAGE_BYTES 32768
#define GSMEM_TOTAL (3 * STAGE_BYTES)

__device__ __forceinline__ void load_stage(unsigned base, int kt, int m0, int n0,
                                           int M, int tid) {
    int k0 = kt * 64;
#pragma unroll
    for (int it = 0; it < 4; it++) {
        int ch = tid + it * 256;            // 1024 chunks of 16B per tile
        int r = ch >> 3, seg = ch & 7;
        unsigned so = SW((unsigned)(r * 128 + seg * 16));
        int gr = m0 + r;
        cpasync16(base + so, &g_xbf[(long long)gr * IN_F + k0 + seg * 8], gr < M);
        cpasync16(base + TB_OFF + so,
                  &g_w1b[(long long)(n0 + r) * IN_F + k0 + seg * 8], 1);
    }
}

__global__ __launch_bounds__(256, 1)
void k_gemm1_bf16(int M) {
    extern __shared__ __align__(128) char sm[];
    unsigned sb = smem_u32(sm);
    int tid = threadIdx.x, wid = tid >> 5, lane = tid & 31;
    int m0 = blockIdx.y * 128, n0 = blockIdx.x * 128;
    int wm = (wid >> 1) * 32;        // warp m-offset (0,32,64,96)
    int wn = (wid & 1) * 64;         // warp n-offset (0,64)
    int gID = lane >> 2, tig = lane & 3;

    float acc[2][8][4];
#pragma unroll
    for (int i = 0; i < 2; i++)
#pragma unroll
        for (int j = 0; j < 8; j++)
#pragma unroll
            for (int q = 0; q < 4; q++) acc[i][j][q] = 0.f;

    // ldmatrix lane addressing (R7-verified patterns, tile-local offsets)
    unsigned a_row = (unsigned)(wm + (lane & 15));
    unsigned a_cb  = (unsigned)((lane >> 4) * 16);
    unsigned b_rowbase = (unsigned)(wn + ((lane >> 4) << 3) + (lane & 7));
    unsigned b_cb = (unsigned)(((lane >> 3) & 1) * 16);

    load_stage(sb, 0, m0, n0, M, tid);
    CP_COMMIT();
    load_stage(sb + STAGE_BYTES, 1, m0, n0, M, tid);
    CP_COMMIT();

    int buf = 0;
    for (int kt = 0; kt < NK64; kt++) {
        unsigned cur = sb + buf * STAGE_BYTES;
        int nb = buf + 2; if (nb >= 3) nb -= 3;
        if (kt + 2 < NK64)
            load_stage(sb + nb * STAGE_BYTES, kt + 2, m0, n0, M, tid);
        CP_COMMIT();
        CP_WAIT2();
        __syncthreads();

#pragma unroll
        for (int ks = 0; ks < 4; ks++) {
            unsigned a[2][4], b[4][4];
            unsigned acb = ks * 32 + a_cb;
#pragma unroll
            for (int mf = 0; mf < 2; mf++)
                ldsm4(a[mf], cur + SW((a_row + mf * 16) * 128 + acb));
            unsigned bcb = ks * 32 + b_cb;
#pragma unroll
            for (int f = 0; f < 4; f++)
                ldsm4(b[f], cur + TB_OFF + SW((b_rowbase + f * 16) * 128 + bcb));
#pragma unroll
            for (int mf = 0; mf < 2; mf++)
#pragma unroll
                for (int f = 0; f < 4; f++) {
                    mma16816(acc[mf][2 * f],     a[mf], &b[f][0]);
                    mma16816(acc[mf][2 * f + 1], a[mf], &b[f][2]);
                }
        }
        __syncthreads();
        buf++; if (buf == 3) buf = 0;
    }

    // epilogue: direct STG.64 of accumulators
#pragma unroll
    for (int mf = 0; mf < 2; mf++) {
        int r0 = m0 + wm + mf * 16 + gID;
#pragma unroll
        for (int nf = 0; nf < 8; nf++) {
            int col = n0 + wn + nf * 8 + tig * 2;
            if (r0 < M)
                *(float2*)&g_h1[(long long)r0 * HID + col] =
                    make_float2(acc[mf][nf][0], acc[mf][nf][1]);
            if (r0 + 8 < M)
                *(float2*)&g_h1[(long long)(r0 + 8) * HID + col] =
                    make_float2(acc[mf][nf][2], acc[mf][nf][3]);
        }
    }
}

// ---------------- SpMM1: r1 = relu( dinv_d * (sum dinv_s h1[s]) + b1 ) ---
__global__ void k_spmm1(const float* __restrict__ b1) {
    int row = blockIdx.x;
    int c = threadIdx.x << 2;
    float di = g_dinv[row];

    float4 v = *(const float4*)&g_h1[(long long)row * HID + c];
    float4 acc;
    acc.x = di * v.x; acc.y = di * v.y; acc.z = di * v.z; acc.w = di * v.w;

    int p0 = g_rowptr[row], p1 = g_rowptr[row + 1];
    for (int p = p0; p < p1; ++p) {
        int s = g_col[p];
        float w = g_dinv[s];
        float4 u = *(const float4*)&g_h1[(long long)s * HID + c];
        acc.x += w * u.x; acc.y += w * u.y; acc.z += w * u.z; acc.w += w * u.w;
    }
    float4 bb = *(const float4*)&b1[c];
    acc.x = fmaxf(acc.x * di + bb.x, 0.f);
    acc.y = fmaxf(acc.y * di + bb.y, 0.f);
    acc.z = fmaxf(acc.z * di + bb.z, 0.f);
    acc.w = fmaxf(acc.w * di + bb.w, 0.f);
    *(float4*)&g_r1[(long long)row * HID + c] = acc;
}

// ---------------- GEMM2: h2 = r1 @ W2  (M x 512 @ 512 x 10) -------------
__global__ void k_gemm2(const float* __restrict__ W2, int Nn) {
    __shared__ float w[HID * NCLS];
    for (int i = threadIdx.x; i < HID * NCLS; i += blockDim.x) w[i] = W2[i];
    __syncthreads();
    int row = blockIdx.x * blockDim.x + threadIdx.x;
    if (row >= Nn) return;
    float acc[NCLS];
#pragma unroll
    for (int j = 0; j < NCLS; j++) acc[j] = 0.f;
    const float4* xr = (const float4*)&g_r1[(long long)row * HID];
#pragma unroll 4
    for (int k4 = 0; k4 < HID / 4; k4++) {
        float4 x = xr[k4];
        const float* w0 = &w[(k4 * 4) * NCLS];
#pragma unroll
        for (int j = 0; j < NCLS; j++)
            acc[j] += x.x * w0[j] + x.y * w0[NCLS + j] +
                      x.z * w0[2 * NCLS + j] + x.w * w0[3 * NCLS + j];
    }
#pragma unroll
    for (int j = 0; j < NCLS; j++) g_h2[(long long)row * NCLS + j] = acc[j];
}

// ---------------- SpMM2 + bias + log_softmax (warp per row) -------------
__global__ void k_spmm2(const float* __restrict__ b2, float* __restrict__ out, int Nn) {
    int row = (blockIdx.x * blockDim.x + threadIdx.x) >> 5;
    int lane = threadIdx.x & 31;
    if (row >= Nn) return;

    float di = g_dinv[row];
    float acc = 0.f;
    if (lane < NCLS) acc = di * g_h2[(long long)row * NCLS + lane];

    int p0 = g_rowptr[row], p1 = g_rowptr[row + 1];
    for (int p = p0; p < p1; ++p) {
        int s = g_col[p];
        float w = g_dinv[s];
        if (lane < NCLS) acc += w * g_h2[(long long)s * NCLS + lane];
    }
    acc = acc * di + ((lane < NCLS) ? b2[lane] : 0.f);

    float v = (lane < NCLS) ? acc : -3.4e38f;
#pragma unroll
    for (int o = 16; o > 0; o >>= 1) v = fmaxf(v, __shfl_xor_sync(0xffffffffu, v, o));
    float ex = (lane < NCLS) ? expf(acc - v) : 0.f;
#pragma unroll
    for (int o = 16; o > 0; o >>= 1) ex += __shfl_xor_sync(0xffffffffu, ex, o);
    float lse = logf(ex);
    if (lane < NCLS) out[(long long)row * NCLS + lane] = acc - v - lse;
}

// ---------------- launch ---------------------------------------------------
extern "C" void kernel_launch(void* const* d_in, const int* in_sizes, int n_in,
                              void* d_out, int out_size) {
    const float* x  = (const float*)d_in[0];
    const int*   ei = (const int*)d_in[1];
    const float* W1 = (const float*)d_in[2];
    const float* b1 = (const float*)d_in[3];
    const float* W2 = (const float*)d_in[4];
    const float* b2 = (const float*)d_in[5];
    float* out = (float*)d_out;

    int Nn = in_sizes[0] / IN_F;          // 20000
    int E  = in_sizes[1] / 2;

    k_detect<<<1, 256>>>(ei, E);
    k_zero  <<<(Nn + 255) / 256, 256>>>(Nn);
    k_count <<<(E + 255) / 256, 256>>>(ei, E);
    k_dinv  <<<(Nn + 255) / 256, 256>>>(Nn);
    k_scan  <<<1, 1024>>>(Nn);
    k_fill  <<<(E + 255) / 256, 256>>>(ei, E);

    long long total4 = (long long)Nn * IN_F / 4;
    k_convA<<<(unsigned)((total4 + 255) / 256), 256>>>(x, total4);
    k_convW<<<(IN_F * HID + 255) / 256, 256>>>(W1);

    cudaFuncSetAttribute(k_gemm1_bf16, cudaFuncAttributeMaxDynamicSharedMemorySize,
                         GSMEM_TOTAL);
    dim3 g1(HID / 128, (Nn + 127) / 128);   // (4, 157)
    k_gemm1_bf16<<<g1, 256, GSMEM_TOTAL>>>(Nn);

    k_spmm1 <<<Nn, 128>>>(b1);
    k_gemm2 <<<(Nn + 127) / 128, 128>>>(W2, Nn);
    k_spmm2 <<<(Nn * 32 + 127) / 128, 128>>>(b2, out, Nn);
}

// round 14
// speedup vs baseline: 4.1223x; 1.0160x over previous
#include <cuda_runtime.h>
#include <cuda_bf16.h>
#include <math.h>

// Problem constants
#define IN_F   4096
#define HID    512
#define NCLS   10
#define NODES_MAX 20000
#define MAX_E  700000
#define NK64   (IN_F / 64)          // 64 K-stages of 64

// ---------------- device scratch (no allocation allowed) ----------------
__device__ int   g_shift;
__device__ int   g_deg[NODES_MAX];
__device__ float g_dinv[NODES_MAX];
__device__ int   g_rowptr[NODES_MAX + 1];
__device__ int   g_cursor[NODES_MAX];
__device__ int   g_col[MAX_E];
__device__ __nv_bfloat16 g_h1b[(long long)NODES_MAX * HID];    // conv1 dense, bf16
__device__ float g_r1[(long long)NODES_MAX * HID];   // relu(A_hat h1 + b1)
__device__ float g_h2[(long long)NODES_MAX * NCLS];
__device__ __nv_bfloat16 g_xbf[(long long)NODES_MAX * IN_F];   // x as bf16
__device__ __nv_bfloat16 g_w1b[(long long)HID * IN_F];         // W1^T bf16 [n][k]

// ---------------- PTX helpers (baseline sm_80+ ISA only) -----------------
__device__ __forceinline__ unsigned smem_u32(const void* p) {
    unsigned a;
    asm("{ .reg .u64 t; cvta.to.shared.u64 t, %1; cvt.u32.u64 %0, t; }"
        : "=r"(a) : "l"(p));
    return a;
}
__device__ __forceinline__ void ldsm4(unsigned* r, unsigned addr) {
    asm volatile("ldmatrix.sync.aligned.m8n8.x4.shared.b16 {%0,%1,%2,%3}, [%4];"
                 : "=r"(r[0]), "=r"(r[1]), "=r"(r[2]), "=r"(r[3]) : "r"(addr));
}
__device__ __forceinline__ void mma16816(float* c, const unsigned* a, const unsigned* b) {
    asm volatile(
        "mma.sync.aligned.m16n8k16.row.col.f32.bf16.bf16.f32 "
        "{%0,%1,%2,%3}, {%4,%5,%6,%7}, {%8,%9}, {%0,%1,%2,%3};"
        : "+f"(c[0]), "+f"(c[1]), "+f"(c[2]), "+f"(c[3])
        : "r"(a[0]), "r"(a[1]), "r"(a[2]), "r"(a[3]), "r"(b[0]), "r"(b[1]));
}
__device__ __forceinline__ void cpasync16(unsigned dst, const void* src, int ok) {
    int sz = ok ? 16 : 0;
    asm volatile("cp.async.cg.shared.global [%0], [%1], 16, %2;"
                 :: "r"(dst), "l"(src), "r"(sz) : "memory");
}
#define CP_COMMIT()  asm volatile("cp.async.commit_group;" ::: "memory")
#define CP_WAIT2()   asm volatile("cp.async.wait_group 2;" ::: "memory")
#define SW(o) ((o) ^ (((o) >> 3) & 0x70))

// ---------------- edge dtype detection ----------------------------------
__global__ void k_detect(const int* __restrict__ ei, int E) {
    __shared__ int s_any;
    if (threadIdx.x == 0) s_any = 0;
    __syncthreads();
    int m = E < 2048 ? E : 2048;
    int nz = 0;
    for (int i = threadIdx.x; i < m; i += blockDim.x) nz |= ei[2 * i + 1];
    if (nz) s_any = 1;
    __syncthreads();
    if (threadIdx.x == 0) g_shift = (s_any == 0) ? 1 : 0;
}
__global__ void k_zero(int n) {
    int i = blockIdx.x * blockDim.x + threadIdx.x;
    if (i < n) g_deg[i] = 0;
}
__global__ void k_count(const int* __restrict__ ei, int E) {
    int e = blockIdx.x * blockDim.x + threadIdx.x;
    if (e < E) {
        int sh = g_shift;
        int d = ei[(E + e) << sh];
        atomicAdd(&g_deg[d], 1);
    }
}
__global__ void k_dinv(int n) {
    int i = blockIdx.x * blockDim.x + threadIdx.x;
    if (i < n) g_dinv[i] = 1.0f / sqrtf((float)(g_deg[i] + 1));
}
__global__ void k_scan(int n) {
    __shared__ int s[1024];
    __shared__ int carry_s;
    int tid = threadIdx.x;
    if (tid == 0) carry_s = 0;
    __syncthreads();
    for (int base = 0; base < n; base += 1024) {
        int i = base + tid;
        int v = (i < n) ? g_deg[i] : 0;
        s[tid] = v;
        __syncthreads();
        for (int off = 1; off < 1024; off <<= 1) {
            int t = (tid >= off) ? s[tid - off] : 0;
            __syncthreads();
            s[tid] += t;
            __syncthreads();
        }
        int carry = carry_s;
        __syncthreads();
        if (tid == 1023) carry_s = carry + s[1023];
        if (i < n) {
            int excl = carry + s[tid] - v;
            g_rowptr[i] = excl;
            g_cursor[i] = excl;
        }
        __syncthreads();
    }
    if (tid == 0) g_rowptr[n] = carry_s;
}
__global__ void k_fill(const int* __restrict__ ei, int E) {
    int e = blockIdx.x * blockDim.x + threadIdx.x;
    if (e < E) {
        int sh = g_shift;
        int s = ei[e << sh];
        int d = ei[(E + e) << sh];
        int pos = atomicAdd(&g_cursor[d], 1);
        g_col[pos] = s;
    }
}

// ---------------- bf16 conversions ---------------------------------------
__global__ void k_convA(const float* __restrict__ x, long long total4) {
    long long i = (long long)blockIdx.x * blockDim.x + threadIdx.x;
    if (i >= total4) return;
    float4 v = ((const float4*)x)[i];
    __nv_bfloat162 a = {__float2bfloat16(v.x), __float2bfloat16(v.y)};
    __nv_bfloat162 b = {__float2bfloat16(v.z), __float2bfloat16(v.w)};
    uint2 u;
    u.x = *(unsigned*)&a; u.y = *(unsigned*)&b;
    *(uint2*)&g_xbf[4 * i] = u;
}
__global__ void k_convW(const float* __restrict__ W1) {
    int idx = blockIdx.x * blockDim.x + threadIdx.x;
    if (idx >= IN_F * HID) return;
    int k = idx / HID, n = idx % HID;       // coalesced read of W1[k][n]
    g_w1b[(long long)n * IN_F + k] = __float2bfloat16(W1[idx]);
}

// ---------------- GEMM1 via mma.sync bf16 single-pass --------------------
// CTA tile M=128 x N=256, BK=64, 512 threads (16 warps, warp tile 32x64),
// SW128-swizzled bf16 SMEM, ldmatrix.x4 frags, cp.async 3-stage pipeline.
#define TB_OFF 16384
#define STAGE_BYTES 49152           // A 16KB + B 32KB
#define GSMEM_TOTAL (3 * STAGE_BYTES)

__device__ __forceinline__ void load_stage(unsigned base, int kt, int m0, int n0,
                                           int M, int tid) {
    int k0 = kt * 64;
#pragma unroll
    for (int it = 0; it < 2; it++) {        // A: 1024 chunks of 16B
        int ch = tid + it * 512;
        int r = ch >> 3, seg = ch & 7;
        unsigned so = SW((unsigned)(r * 128 + seg * 16));
        int gr = m0 + r;
        cpasync16(base + so, &g_xbf[(long long)gr * IN_F + k0 + seg * 8], gr < M);
    }
#pragma unroll
    for (int it = 0; it < 4; it++) {        // B: 2048 chunks (256 n-rows)
        int ch = tid + it * 512;
        int r = ch >> 3, seg = ch & 7;
        unsigned so = SW((unsigned)(r * 128 + seg * 16));
        cpasync16(base + TB_OFF + so,
                  &g_w1b[(long long)(n0 + r) * IN_F + k0 + seg * 8], 1);
    }
}

__global__ __launch_bounds__(512, 1)
void k_gemm1_bf16(int M) {
    extern __shared__ __align__(128) char sm[];
    unsigned sb = smem_u32(sm);
    int tid = threadIdx.x, wid = tid >> 5, lane = tid & 31;
    int m0 = blockIdx.y * 128, n0 = blockIdx.x * 256;
    int wm = (wid >> 2) * 32;        // warp m-offset (0,32,64,96)
    int wn = (wid & 3) * 64;         // warp n-offset (0,64,128,192)
    int gID = lane >> 2, tig = lane & 3;

    float acc[2][8][4];
#pragma unroll
    for (int i = 0; i < 2; i++)
#pragma unroll
        for (int j = 0; j < 8; j++)
#pragma unroll
            for (int q = 0; q < 4; q++) acc[i][j][q] = 0.f;

    // ldmatrix lane addressing (verified patterns, tile-local offsets)
    unsigned a_row = (unsigned)(wm + (lane & 15));
    unsigned a_cb  = (unsigned)((lane >> 4) * 16);
    unsigned b_rowbase = (unsigned)(wn + ((lane >> 4) << 3) + (lane & 7));
    unsigned b_cb = (unsigned)(((lane >> 3) & 1) * 16);

    load_stage(sb, 0, m0, n0, M, tid);
    CP_COMMIT();
    load_stage(sb + STAGE_BYTES, 1, m0, n0, M, tid);
    CP_COMMIT();

    int buf = 0;
    for (int kt = 0; kt < NK64; kt++) {
        unsigned cur = sb + buf * STAGE_BYTES;
        int nb = buf + 2; if (nb >= 3) nb -= 3;
        if (kt + 2 < NK64)
            load_stage(sb + nb * STAGE_BYTES, kt + 2, m0, n0, M, tid);
        CP_COMMIT();
        CP_WAIT2();
        __syncthreads();

#pragma unroll
        for (int ks = 0; ks < 4; ks++) {
            unsigned a[2][4], b[4][4];
            unsigned acb = ks * 32 + a_cb;
#pragma unroll
            for (int mf = 0; mf < 2; mf++)
                ldsm4(a[mf], cur + SW((a_row + mf * 16) * 128 + acb));
            unsigned bcb = ks * 32 + b_cb;
#pragma unroll
            for (int f = 0; f < 4; f++)
                ldsm4(b[f], cur + TB_OFF + SW((b_rowbase + f * 16) * 128 + bcb));
#pragma unroll
            for (int mf = 0; mf < 2; mf++)
#pragma unroll
                for (int f = 0; f < 4; f++) {
                    mma16816(acc[mf][2 * f],     a[mf], &b[f][0]);
                    mma16816(acc[mf][2 * f + 1], a[mf], &b[f][2]);
                }
        }
        __syncthreads();
        buf++; if (buf == 3) buf = 0;
    }

    // epilogue: convert accumulators to bf16, STG.32 per fragment row-pair
#pragma unroll
    for (int mf = 0; mf < 2; mf++) {
        int r0 = m0 + wm + mf * 16 + gID;
#pragma unroll
        for (int nf = 0; nf < 8; nf++) {
            int col = n0 + wn + nf * 8 + tig * 2;
            if (r0 < M) {
                __nv_bfloat162 h = __float22bfloat162_rn(
                    make_float2(acc[mf][nf][0], acc[mf][nf][1]));
                *(unsigned*)&g_h1b[(long long)r0 * HID + col] = *(unsigned*)&h;
            }
            if (r0 + 8 < M) {
                __nv_bfloat162 h = __float22bfloat162_rn(
                    make_float2(acc[mf][nf][2], acc[mf][nf][3]));
                *(unsigned*)&g_h1b[(long long)(r0 + 8) * HID + col] = *(unsigned*)&h;
            }
        }
    }
}

// ---------------- SpMM1: r1 = relu( dinv_d * (sum dinv_s h1[s]) + b1 ) ---
// one block of 128 threads per dst row; each thread owns 4 contiguous cols
__global__ void k_spmm1(const float* __restrict__ b1) {
    int row = blockIdx.x;
    int c = threadIdx.x << 2;
    float di = g_dinv[row];

    uint2 u0 = *(const uint2*)&g_h1b[(long long)row * HID + c];
    float2 vlo = __bfloat1622float2(*(__nv_bfloat162*)&u0.x);
    float2 vhi = __bfloat1622float2(*(__nv_bfloat162*)&u0.y);
    float4 acc;
    acc.x = di * vlo.x; acc.y = di * vlo.y; acc.z = di * vhi.x; acc.w = di * vhi.y;

    int p0 = g_rowptr[row], p1 = g_rowptr[row + 1];
    for (int p = p0; p < p1; ++p) {
        int s = g_col[p];
        float w = g_dinv[s];
        uint2 u = *(const uint2*)&g_h1b[(long long)s * HID + c];
        float2 a = __bfloat1622float2(*(__nv_bfloat162*)&u.x);
        float2 b = __bfloat1622float2(*(__nv_bfloat162*)&u.y);
        acc.x += w * a.x; acc.y += w * a.y; acc.z += w * b.x; acc.w += w * b.y;
    }
    float4 bb = *(const float4*)&b1[c];
    acc.x = fmaxf(acc.x * di + bb.x, 0.f);
    acc.y = fmaxf(acc.y * di + bb.y, 0.f);
    acc.z = fmaxf(acc.z * di + bb.z, 0.f);
    acc.w = fmaxf(acc.w * di + bb.w, 0.f);
    *(float4*)&g_r1[(long long)row * HID + c] = acc;
}

// ---------------- GEMM2: h2 = r1 @ W2  (M x 512 @ 512 x 10) -------------
__global__ void k_gemm2(const float* __restrict__ W2, int Nn) {
    __shared__ float w[HID * NCLS];
    for (int i = threadIdx.x; i < HID * NCLS; i += blockDim.x) w[i] = W2[i];
    __syncthreads();
    int row = blockIdx.x * blockDim.x + threadIdx.x;
    if (row >= Nn) return;
    float acc[NCLS];
#pragma unroll
    for (int j = 0; j < NCLS; j++) acc[j] = 0.f;
    const float4* xr = (const float4*)&g_r1[(long long)row * HID];
#pragma unroll 4
    for (int k4 = 0; k4 < HID / 4; k4++) {
        float4 x = xr[k4];
        const float* w0 = &w[(k4 * 4) * NCLS];
#pragma unroll
        for (int j = 0; j < NCLS; j++)
            acc[j] += x.x * w0[j] + x.y * w0[NCLS + j] +
                      x.z * w0[2 * NCLS + j] + x.w * w0[3 * NCLS + j];
    }
#pragma unroll
    for (int j = 0; j < NCLS; j++) g_h2[(long long)row * NCLS + j] = acc[j];
}

// ---------------- SpMM2 + bias + log_softmax (warp per row) -------------
__global__ void k_spmm2(const float* __restrict__ b2, float* __restrict__ out, int Nn) {
    int row = (blockIdx.x * blockDim.x + threadIdx.x) >> 5;
    int lane = threadIdx.x & 31;
    if (row >= Nn) return;

    float di = g_dinv[row];
    float acc = 0.f;
    if (lane < NCLS) acc = di * g_h2[(long long)row * NCLS + lane];

    int p0 = g_rowptr[row], p1 = g_rowptr[row + 1];
    for (int p = p0; p < p1; ++p) {
        int s = g_col[p];
        float w = g_dinv[s];
        if (lane < NCLS) acc += w * g_h2[(long long)s * NCLS + lane];
    }
    acc = acc * di + ((lane < NCLS) ? b2[lane] : 0.f);

    float v = (lane < NCLS) ? acc : -3.4e38f;
#pragma unroll
    for (int o = 16; o > 0; o >>= 1) v = fmaxf(v, __shfl_xor_sync(0xffffffffu, v, o));
    float ex = (lane < NCLS) ? expf(acc - v) : 0.f;
#pragma unroll
    for (int o = 16; o > 0; o >>= 1) ex += __shfl_xor_sync(0xffffffffu, ex, o);
    float lse = logf(ex);
    if (lane < NCLS) out[(long long)row * NCLS + lane] = acc - v - lse;
}

// ---------------- launch ---------------------------------------------------
extern "C" void kernel_launch(void* const* d_in, const int* in_sizes, int n_in,
                              void* d_out, int out_size) {
    const float* x  = (const float*)d_in[0];
    const int*   ei = (const int*)d_in[1];
    const float* W1 = (const float*)d_in[2];
    const float* b1 = (const float*)d_in[3];
    const float* W2 = (const float*)d_in[4];
    const float* b2 = (const float*)d_in[5];
    float* out = (float*)d_out;

    int Nn = in_sizes[0] / IN_F;          // 20000
    int E  = in_sizes[1] / 2;

    k_detect<<<1, 256>>>(ei, E);
    k_zero  <<<(Nn + 255) / 256, 256>>>(Nn);
    k_count <<<(E + 255) / 256, 256>>>(ei, E);
    k_dinv  <<<(Nn + 255) / 256, 256>>>(Nn);
    k_scan  <<<1, 1024>>>(Nn);
    k_fill  <<<(E + 255) / 256, 256>>>(ei, E);

    long long total4 = (long long)Nn * IN_F / 4;
    k_convA<<<(unsigned)((total4 + 255) / 256), 256>>>(x, total4);
    k_convW<<<(IN_F * HID + 255) / 256, 256>>>(W1);

    cudaFuncSetAttribute(k_gemm1_bf16, cudaFuncAttributeMaxDynamicSharedMemorySize,
                         GSMEM_TOTAL);
    dim3 g1(HID / 256, (Nn + 127) / 128);   // (2, 157)
    k_gemm1_bf16<<<g1, 512, GSMEM_TOTAL>>>(Nn);

    k_spmm1 <<<Nn, 128>>>(b1);
    k_gemm2 <<<(Nn + 127) / 128, 128>>>(W2, Nn);
    k_spmm2 <<<(Nn * 32 + 127) / 128, 128>>>(b2, out, Nn);
}

// round 15
// speedup vs baseline: 4.1836x; 1.0149x over previous
#include <cuda_runtime.h>
#include <cuda_fp16.h>
#include <math.h>

// Problem constants
#define IN_F   4096
#define HID    512
#define NCLS   10
#define NODES_MAX 20000
#define MAX_E  700000
#define NK64   (IN_F / 64)          // 64 K-stages of 64

// ---------------- device scratch (no allocation allowed) ----------------
__device__ int   g_shift;
__device__ int   g_deg[NODES_MAX];
__device__ float g_dinv[NODES_MAX];
__device__ int   g_rowptr[NODES_MAX + 1];
__device__ int   g_cursor[NODES_MAX];
__device__ int   g_col[MAX_E];
__device__ __half g_h1h[(long long)NODES_MAX * HID];   // conv1 dense, fp16
__device__ float g_h2[(long long)NODES_MAX * NCLS];
__device__ __half g_xh[(long long)NODES_MAX * IN_F];   // x as fp16
__device__ __half g_w1h[(long long)HID * IN_F];        // W1^T fp16 [n][k]

// ---------------- PTX helpers (baseline sm_80+ ISA only) -----------------
__device__ __forceinline__ unsigned smem_u32(const void* p) {
    unsigned a;
    asm("{ .reg .u64 t; cvta.to.shared.u64 t, %1; cvt.u32.u64 %0, t; }"
        : "=r"(a) : "l"(p));
    return a;
}
__device__ __forceinline__ void ldsm4(unsigned* r, unsigned addr) {
    asm volatile("ldmatrix.sync.aligned.m8n8.x4.shared.b16 {%0,%1,%2,%3}, [%4];"
                 : "=r"(r[0]), "=r"(r[1]), "=r"(r[2]), "=r"(r[3]) : "r"(addr));
}
__device__ __forceinline__ void mma16816(float* c, const unsigned* a, const unsigned* b) {
    asm volatile(
        "mma.sync.aligned.m16n8k16.row.col.f32.f16.f16.f32 "
        "{%0,%1,%2,%3}, {%4,%5,%6,%7}, {%8,%9}, {%0,%1,%2,%3};"
        : "+f"(c[0]), "+f"(c[1]), "+f"(c[2]), "+f"(c[3])
        : "r"(a[0]), "r"(a[1]), "r"(a[2]), "r"(a[3]), "r"(b[0]), "r"(b[1]));
}
__device__ __forceinline__ void cpasync16(unsigned dst, const void* src, int ok) {
    int sz = ok ? 16 : 0;
    asm volatile("cp.async.cg.shared.global [%0], [%1], 16, %2;"
                 :: "r"(dst), "l"(src), "r"(sz) : "memory");
}
#define CP_COMMIT()  asm volatile("cp.async.commit_group;" ::: "memory")
#define CP_WAIT2()   asm volatile("cp.async.wait_group 2;" ::: "memory")
#define SW(o) ((o) ^ (((o) >> 3) & 0x70))

// ---------------- edge dtype detection ----------------------------------
__global__ void k_detect(const int* __restrict__ ei, int E) {
    __shared__ int s_any;
    if (threadIdx.x == 0) s_any = 0;
    __syncthreads();
    int m = E < 2048 ? E : 2048;
    int nz = 0;
    for (int i = threadIdx.x; i < m; i += blockDim.x) nz |= ei[2 * i + 1];
    if (nz) s_any = 1;
    __syncthreads();
    if (threadIdx.x == 0) g_shift = (s_any == 0) ? 1 : 0;
}
__global__ void k_zero(int n) {
    int i = blockIdx.x * blockDim.x + threadIdx.x;
    if (i < n) g_deg[i] = 0;
}

// ---------------- fused prep: convA | convW | count ----------------------
__global__ void k_prep(const float* __restrict__ x, const float* __restrict__ W1,
                       const int* __restrict__ ei, int E,
                       long long total4, int nConvA, int nConvW) {
    int b = blockIdx.x, tid = threadIdx.x;
    if (b < nConvA) {
        long long i = (long long)b * 256 + tid;
        if (i < total4) {
            float4 v = ((const float4*)x)[i];
            __half2 a = __floats2half2_rn(v.x, v.y);
            __half2 c = __floats2half2_rn(v.z, v.w);
            uint2 u;
            u.x = *(unsigned*)&a; u.y = *(unsigned*)&c;
            *(uint2*)&g_xh[4 * i] = u;
        }
    } else if (b < nConvA + nConvW) {
        int idx = (b - nConvA) * 256 + tid;
        if (idx < IN_F * HID) {
            int k = idx / HID, n = idx % HID;   // coalesced read of W1[k][n]
            g_w1h[(long long)n * IN_F + k] = __float2half_rn(W1[idx]);
        }
    } else {
        int e = (b - nConvA - nConvW) * 256 + tid;
        if (e < E) {
            int sh = g_shift;
            int d = ei[(E + e) << sh];
            atomicAdd(&g_deg[d], 1);
        }
    }
}

// ---------------- fused scan (block 0) + dinv (blocks 1..) ---------------
__global__ void k_scan_dinv(int n) {
    if (blockIdx.x > 0) {
        int i = (blockIdx.x - 1) * 1024 + threadIdx.x;
        if (i < n) g_dinv[i] = 1.0f / sqrtf((float)(g_deg[i] + 1));
        return;
    }
    __shared__ int s[1024];
    __shared__ int carry_s;
    int tid = threadIdx.x;
    if (tid == 0) carry_s = 0;
    __syncthreads();
    for (int base = 0; base < n; base += 1024) {
        int i = base + tid;
        int v = (i < n) ? g_deg[i] : 0;
        s[tid] = v;
        __syncthreads();
        for (int off = 1; off < 1024; off <<= 1) {
            int t = (tid >= off) ? s[tid - off] : 0;
            __syncthreads();
            s[tid] += t;
            __syncthreads();
        }
        int carry = carry_s;
        __syncthreads();
        if (tid == 1023) carry_s = carry + s[1023];
        if (i < n) {
            int excl = carry + s[tid] - v;
            g_rowptr[i] = excl;
            g_cursor[i] = excl;
        }
        __syncthreads();
    }
    if (tid == 0) g_rowptr[n] = carry_s;
}
__global__ void k_fill(const int* __restrict__ ei, int E) {
    int e = blockIdx.x * blockDim.x + threadIdx.x;
    if (e < E) {
        int sh = g_shift;
        int s = ei[e << sh];
        int d = ei[(E + e) << sh];
        int pos = atomicAdd(&g_cursor[d], 1);
        g_col[pos] = s;
    }
}

// ---------------- GEMM1 via mma.sync fp16 single-pass --------------------
// CTA tile M=128 x N=128, BK=64, 256 threads (8 warps, warp tile 32x64),
// SW128-swizzled fp16 SMEM, ldmatrix.x4 frags, cp.async 3-stage pipeline.
#define TB_OFF 16384
#define STAGE_BYTES 32768
#define GSMEM_TOTAL (3 * STAGE_BYTES)

__device__ __forceinline__ void load_stage(unsigned base, int kt, int m0, int n0,
                                           int M, int tid) {
    int k0 = kt * 64;
#pragma unroll
    for (int it = 0; it < 4; it++) {
        int ch = tid + it * 256;            // 1024 chunks of 16B per tile
        int r = ch >> 3, seg = ch & 7;
        unsigned so = SW((unsigned)(r * 128 + seg * 16));
        int gr = m0 + r;
        cpasync16(base + so, &g_xh[(long long)gr * IN_F + k0 + seg * 8], gr < M);
        cpasync16(base + TB_OFF + so,
                  &g_w1h[(long long)(n0 + r) * IN_F + k0 + seg * 8], 1);
    }
}

__global__ __launch_bounds__(256)
void k_gemm1_f16(int M) {
    extern __shared__ __align__(128) char sm[];
    unsigned sb = smem_u32(sm);
    int tid = threadIdx.x, wid = tid >> 5, lane = tid & 31;
    int m0 = blockIdx.y * 128, n0 = blockIdx.x * 128;
    int wm = (wid >> 1) * 32;        // warp m-offset (0,32,64,96)
    int wn = (wid & 1) * 64;         // warp n-offset (0,64)
    int gID = lane >> 2, tig = lane & 3;

    float acc[2][8][4];
#pragma unroll
    for (int i = 0; i < 2; i++)
#pragma unroll
        for (int j = 0; j < 8; j++)
#pragma unroll
            for (int q = 0; q < 4; q++) acc[i][j][q] = 0.f;

    unsigned a_row = (unsigned)(wm + (lane & 15));
    unsigned a_cb  = (unsigned)((lane >> 4) * 16);
    unsigned b_rowbase = (unsigned)(wn + ((lane >> 4) << 3) + (lane & 7));
    unsigned b_cb = (unsigned)(((lane >> 3) & 1) * 16);

    load_stage(sb, 0, m0, n0, M, tid);
    CP_COMMIT();
    load_stage(sb + STAGE_BYTES, 1, m0, n0, M, tid);
    CP_COMMIT();

    int buf = 0;
    for (int kt = 0; kt < NK64; kt++) {
        unsigned cur = sb + buf * STAGE_BYTES;
        int nb = buf + 2; if (nb >= 3) nb -= 3;
        if (kt + 2 < NK64)
            load_stage(sb + nb * STAGE_BYTES, kt + 2, m0, n0, M, tid);
        CP_COMMIT();
        CP_WAIT2();
        __syncthreads();

#pragma unroll
        for (int ks = 0; ks < 4; ks++) {
            unsigned a[2][4], b[4][4];
            unsigned acb = ks * 32 + a_cb;
#pragma unroll
            for (int mf = 0; mf < 2; mf++)
                ldsm4(a[mf], cur + SW((a_row + mf * 16) * 128 + acb));
            unsigned bcb = ks * 32 + b_cb;
#pragma unroll
            for (int f = 0; f < 4; f++)
                ldsm4(b[f], cur + TB_OFF + SW((b_rowbase + f * 16) * 128 + bcb));
#pragma unroll
            for (int mf = 0; mf < 2; mf++)
#pragma unroll
                for (int f = 0; f < 4; f++) {
                    mma16816(acc[mf][2 * f],     a[mf], &b[f][0]);
                    mma16816(acc[mf][2 * f + 1], a[mf], &b[f][2]);
                }
        }
        __syncthreads();
        buf++; if (buf == 3) buf = 0;
    }

    // epilogue: convert accumulators to fp16, STG.32 per fragment row-pair
#pragma unroll
    for (int mf = 0; mf < 2; mf++) {
        int r0 = m0 + wm + mf * 16 + gID;
#pragma unroll
        for (int nf = 0; nf < 8; nf++) {
            int col = n0 + wn + nf * 8 + tig * 2;
            if (r0 < M) {
                __half2 h = __floats2half2_rn(acc[mf][nf][0], acc[mf][nf][1]);
                *(unsigned*)&g_h1h[(long long)r0 * HID + col] = *(unsigned*)&h;
            }
            if (r0 + 8 < M) {
                __half2 h = __floats2half2_rn(acc[mf][nf][2], acc[mf][nf][3]);
                *(unsigned*)&g_h1h[(long long)(r0 + 8) * HID + col] = *(unsigned*)&h;
            }
        }
    }
}

// ---------------- fused SpMM1 + GEMM2 ------------------------------------
// One 128-thread block per dst row. Gather+normalize+relu r1 row in regs,
// then h2[row] = r1row @ W2 via per-thread partials + block tree reduction.
__global__ void k_spmm1g2(const float* __restrict__ b1, const float* __restrict__ W2) {
    __shared__ float w2s[HID * NCLS];     // 20480 B
    __shared__ float red[NCLS * 128];     // 5120 B
    int row = blockIdx.x, t = threadIdx.x;
    for (int i = t; i < HID * NCLS; i += 128) w2s[i] = W2[i];

    int c = t << 2;
    float di = g_dinv[row];

    uint2 u0 = *(const uint2*)&g_h1h[(long long)row * HID + c];
    float2 vlo = __half22float2(*(__half2*)&u0.x);
    float2 vhi = __half22float2(*(__half2*)&u0.y);
    float4 acc;
    acc.x = di * vlo.x; acc.y = di * vlo.y; acc.z = di * vhi.x; acc.w = di * vhi.y;

    int p0 = g_rowptr[row], p1 = g_rowptr[row + 1];
    for (int p = p0; p < p1; ++p) {
        int s = g_col[p];
        float w = g_dinv[s];
        uint2 u = *(const uint2*)&g_h1h[(long long)s * HID + c];
        float2 a = __half22float2(*(__half2*)&u.x);
        float2 b = __half22float2(*(__half2*)&u.y);
        acc.x += w * a.x; acc.y += w * a.y; acc.z += w * b.x; acc.w += w * b.y;
    }
    float4 bb = *(const float4*)&b1[c];
    acc.x = fmaxf(acc.x * di + bb.x, 0.f);
    acc.y = fmaxf(acc.y * di + bb.y, 0.f);
    acc.z = fmaxf(acc.z * di + bb.z, 0.f);
    acc.w = fmaxf(acc.w * di + bb.w, 0.f);

    __syncthreads();   // w2s ready (and red not yet in use)

    const float* w0 = &w2s[c * NCLS];
    float pjs[NCLS];
#pragma unroll
    for (int j = 0; j < NCLS; j++)
        pjs[j] = acc.x * w0[j] + acc.y * w0[NCLS + j] +
                 acc.z * w0[2 * NCLS + j] + acc.w * w0[3 * NCLS + j];
#pragma unroll
    for (int j = 0; j < NCLS; j++) red[j * 128 + t] = pjs[j];
    __syncthreads();
#pragma unroll
    for (int s = 64; s > 0; s >>= 1) {
        if (t < s)
#pragma unroll
            for (int j = 0; j < NCLS; j++)
                red[j * 128 + t] += red[j * 128 + t + s];
        __syncthreads();
    }
    if (t < NCLS) g_h2[(long long)row * NCLS + t] = red[t * 128];
}

// ---------------- SpMM2 + bias + log_softmax (warp per row) -------------
__global__ void k_spmm2(const float* __restrict__ b2, float* __restrict__ out, int Nn) {
    int row = (blockIdx.x * blockDim.x + threadIdx.x) >> 5;
    int lane = threadIdx.x & 31;
    if (row >= Nn) return;

    float di = g_dinv[row];
    float acc = 0.f;
    if (lane < NCLS) acc = di * g_h2[(long long)row * NCLS + lane];

    int p0 = g_rowptr[row], p1 = g_rowptr[row + 1];
    for (int p = p0; p < p1; ++p) {
        int s = g_col[p];
        float w = g_dinv[s];
        if (lane < NCLS) acc += w * g_h2[(long long)s * NCLS + lane];
    }
    acc = acc * di + ((lane < NCLS) ? b2[lane] : 0.f);

    float v = (lane < NCLS) ? acc : -3.4e38f;
#pragma unroll
    for (int o = 16; o > 0; o >>= 1) v = fmaxf(v, __shfl_xor_sync(0xffffffffu, v, o));
    float ex = (lane < NCLS) ? expf(acc - v) : 0.f;
#pragma unroll
    for (int o = 16; o > 0; o >>= 1) ex += __shfl_xor_sync(0xffffffffu, ex, o);
    float lse = logf(ex);
    if (lane < NCLS) out[(long long)row * NCLS + lane] = acc - v - lse;
}

// ---------------- launch ---------------------------------------------------
extern "C" void kernel_launch(void* const* d_in, const int* in_sizes, int n_in,
                              void* d_out, int out_size) {
    const float* x  = (const float*)d_in[0];
    const int*   ei = (const int*)d_in[1];
    const float* W1 = (const float*)d_in[2];
    const float* b1 = (const float*)d_in[3];
    const float* W2 = (const float*)d_in[4];
    const float* b2 = (const float*)d_in[5];
    float* out = (float*)d_out;

    int Nn = in_sizes[0] / IN_F;          // 20000
    int E  = in_sizes[1] / 2;

    k_detect<<<1, 256>>>(ei, E);
    k_zero  <<<(Nn + 255) / 256, 256>>>(Nn);

    long long total4 = (long long)Nn * IN_F / 4;
    int nConvA = (int)((total4 + 255) / 256);
    int nConvW = (IN_F * HID + 255) / 256;
    int nCount = (E + 255) / 256;
    k_prep<<<nConvA + nConvW + nCount, 256>>>(x, W1, ei, E, total4, nConvA, nConvW);

    k_scan_dinv<<<1 + (Nn + 1023) / 1024, 1024>>>(Nn);
    k_fill<<<(E + 255) / 256, 256>>>(ei, E);

    cudaFuncSetAttribute(k_gemm1_f16, cudaFuncAttributeMaxDynamicSharedMemorySize,
                         GSMEM_TOTAL);
    dim3 g1(HID / 128, (Nn + 127) / 128);   // (4, 157)
    k_gemm1_f16<<<g1, 256, GSMEM_TOTAL>>>(Nn);

    k_spmm1g2<<<Nn, 128>>>(b1, W2);
    k_spmm2<<<(Nn * 32 + 127) / 128, 128>>>(b2, out, Nn);
}

// round 17
// speedup vs baseline: 5.2350x; 1.2513x over previous
#include <cuda_runtime.h>
#include <cuda_fp16.h>
#include <math.h>

// Problem constants
#define IN_F   4096
#define HID    512
#define NCLS   10
#define NODES_MAX 20000
#define MAX_E  700000
#define NK64   (IN_F / 64)          // 64 K-stages of 64

// ---------------- device scratch (no allocation allowed) ----------------
__device__ int   g_shift;
__device__ int   g_deg[NODES_MAX];
__device__ float g_dinv[NODES_MAX];
__device__ int   g_rowptr[NODES_MAX + 1];
__device__ int   g_cursor[NODES_MAX];
__device__ int   g_col[MAX_E];
__device__ __half g_h1h[(long long)NODES_MAX * HID];   // conv1 dense, fp16
__device__ __half g_r1h[(long long)NODES_MAX * HID];   // relu row, fp16
__device__ float g_h2[(long long)NODES_MAX * NCLS];
__device__ __half g_xh[(long long)NODES_MAX * IN_F];   // x as fp16
__device__ __half g_w1h[(long long)HID * IN_F];        // W1^T fp16 [n][k]

// ---------------- PTX helpers (baseline sm_80+ ISA only) -----------------
__device__ __forceinline__ unsigned smem_u32(const void* p) {
    unsigned a;
    asm("{ .reg .u64 t; cvta.to.shared.u64 t, %1; cvt.u32.u64 %0, t; }"
        : "=r"(a) : "l"(p));
    return a;
}
__device__ __forceinline__ void ldsm4(unsigned* r, unsigned addr) {
    asm volatile("ldmatrix.sync.aligned.m8n8.x4.shared.b16 {%0,%1,%2,%3}, [%4];"
                 : "=r"(r[0]), "=r"(r[1]), "=r"(r[2]), "=r"(r[3]) : "r"(addr));
}
__device__ __forceinline__ void mma16816(float* c, const unsigned* a, const unsigned* b) {
    asm volatile(
        "mma.sync.aligned.m16n8k16.row.col.f32.f16.f16.f32 "
        "{%0,%1,%2,%3}, {%4,%5,%6,%7}, {%8,%9}, {%0,%1,%2,%3};"
        : "+f"(c[0]), "+f"(c[1]), "+f"(c[2]), "+f"(c[3])
        : "r"(a[0]), "r"(a[1]), "r"(a[2]), "r"(a[3]), "r"(b[0]), "r"(b[1]));
}
__device__ __forceinline__ void cpasync16(unsigned dst, const void* src, int ok) {
    int sz = ok ? 16 : 0;
    asm volatile("cp.async.cg.shared.global [%0], [%1], 16, %2;"
                 :: "r"(dst), "l"(src), "r"(sz) : "memory");
}
#define CP_COMMIT()  asm volatile("cp.async.commit_group;" ::: "memory")
#define CP_WAIT2()   asm volatile("cp.async.wait_group 2;" ::: "memory")
#define SW(o) ((o) ^ (((o) >> 3) & 0x70))

// ---------------- edge dtype detection ----------------------------------
__global__ void k_detect(const int* __restrict__ ei, int E) {
    __shared__ int s_any;
    if (threadIdx.x == 0) s_any = 0;
    __syncthreads();
    int m = E < 2048 ? E : 2048;
    int nz = 0;
    for (int i = threadIdx.x; i < m; i += blockDim.x) nz |= ei[2 * i + 1];
    if (nz) s_any = 1;
    __syncthreads();
    if (threadIdx.x == 0) g_shift = (s_any == 0) ? 1 : 0;
}
__global__ void k_zero(int n) {
    int i = blockIdx.x * blockDim.x + threadIdx.x;
    if (i < n) g_deg[i] = 0;
}
__global__ void k_count(const int* __restrict__ ei, int E) {
    int e = blockIdx.x * blockDim.x + threadIdx.x;
    if (e < E) {
        int sh = g_shift;
        int d = ei[(E + e) << sh];
        atomicAdd(&g_deg[d], 1);
    }
}
// fused scan (block 0) + dinv (blocks 1..)
__global__ void k_scan_dinv(int n) {
    if (blockIdx.x > 0) {
        int i = (blockIdx.x - 1) * 1024 + threadIdx.x;
        if (i < n) g_dinv[i] = 1.0f / sqrtf((float)(g_deg[i] + 1));
        return;
    }
    __shared__ int s[1024];
    __shared__ int carry_s;
    int tid = threadIdx.x;
    if (tid == 0) carry_s = 0;
    __syncthreads();
    for (int base = 0; base < n; base += 1024) {
        int i = base + tid;
        int v = (i < n) ? g_deg[i] : 0;
        s[tid] = v;
        __syncthreads();
        for (int off = 1; off < 1024; off <<= 1) {
            int t = (tid >= off) ? s[tid - off] : 0;
            __syncthreads();
            s[tid] += t;
            __syncthreads();
        }
        int carry = carry_s;
        __syncthreads();
        if (tid == 1023) carry_s = carry + s[1023];
        if (i < n) {
            int excl = carry + s[tid] - v;
            g_rowptr[i] = excl;
            g_cursor[i] = excl;
        }
        __syncthreads();
    }
    if (tid == 0) g_rowptr[n] = carry_s;
}
__global__ void k_fill(const int* __restrict__ ei, int E) {
    int e = blockIdx.x * blockDim.x + threadIdx.x;
    if (e < E) {
        int sh = g_shift;
        int s = ei[e << sh];
        int d = ei[(E + e) << sh];
        int pos = atomicAdd(&g_cursor[d], 1);
        g_col[pos] = s;
    }
}

// ---------------- fused conv: x->fp16 | W1 transpose (coalesced) ---------
__global__ void k_conv(const float* __restrict__ x, const float* __restrict__ W1,
                       long long total4, int nConvA) {
    __shared__ float tile[32][33];
    int b = blockIdx.x, t = threadIdx.x;
    if (b < nConvA) {
        long long i = (long long)b * 256 + t;
        if (i < total4) {
            float4 v = ((const float4*)x)[i];
            __half2 a = __floats2half2_rn(v.x, v.y);
            __half2 c = __floats2half2_rn(v.z, v.w);
            uint2 u;
            u.x = *(unsigned*)&a; u.y = *(unsigned*)&c;
            *(uint2*)&g_xh[4 * i] = u;
        }
        return;
    }
    // transpose blocks: 2048 tiles of 32x32 (k-major in, n-major out)
    int b2 = b - nConvA;
    int k0 = (b2 >> 4) * 32;        // 128 k-tiles
    int n0 = (b2 & 15) * 32;        // 16 n-tiles
    int c = t & 31, r8 = t >> 5;    // 8 rows per pass
#pragma unroll
    for (int i = 0; i < 4; i++) {
        int r = r8 + 8 * i;
        tile[r][c] = W1[(long long)(k0 + r) * HID + n0 + c];
    }
    __syncthreads();
#pragma unroll
    for (int i = 0; i < 4; i++) {
        int r = r8 + 8 * i;
        g_w1h[(long long)(n0 + r) * IN_F + k0 + c] = __float2half_rn(tile[c][r]);
    }
}

// ---------------- GEMM1 via mma.sync fp16 single-pass --------------------
// CTA tile M=128 x N=128, BK=64, 256 threads (8 warps, warp tile 32x64),
// SW128-swizzled fp16 SMEM, ldmatrix.x4 frags, cp.async 3-stage pipeline.
#define TB_OFF 16384
#define STAGE_BYTES 32768
#define GSMEM_TOTAL (3 * STAGE_BYTES)

__device__ __forceinline__ void load_stage(unsigned base, int kt, int m0, int n0,
                                           int M, int tid) {
    int k0 = kt * 64;
#pragma unroll
    for (int it = 0; it < 4; it++) {
        int ch = tid + it * 256;            // 1024 chunks of 16B per tile
        int r = ch >> 3, seg = ch & 7;
        unsigned so = SW((unsigned)(r * 128 + seg * 16));
        int gr = m0 + r;
        cpasync16(base + so, &g_xh[(long long)gr * IN_F + k0 + seg * 8], gr < M);
        cpasync16(base + TB_OFF + so,
                  &g_w1h[(long long)(n0 + r) * IN_F + k0 + seg * 8], 1);
    }
}

__global__ __launch_bounds__(256)
void k_gemm1_f16(int M) {
    extern __shared__ __align__(128) char sm[];
    unsigned sb = smem_u32(sm);
    int tid = threadIdx.x, wid = tid >> 5, lane = tid & 31;
    int m0 = blockIdx.y * 128, n0 = blockIdx.x * 128;
    int wm = (wid >> 1) * 32;
    int wn = (wid & 1) * 64;
    int gID = lane >> 2, tig = lane & 3;

    float acc[2][8][4];
#pragma unroll
    for (int i = 0; i < 2; i++)
#pragma unroll
        for (int j = 0; j < 8; j++)
#pragma unroll
            for (int q = 0; q < 4; q++) acc[i][j][q] = 0.f;

    unsigned a_row = (unsigned)(wm + (lane & 15));
    unsigned a_cb  = (unsigned)((lane >> 4) * 16);
    unsigned b_rowbase = (unsigned)(wn + ((lane >> 4) << 3) + (lane & 7));
    unsigned b_cb = (unsigned)(((lane >> 3) & 1) * 16);

    load_stage(sb, 0, m0, n0, M, tid);
    CP_COMMIT();
    load_stage(sb + STAGE_BYTES, 1, m0, n0, M, tid);
    CP_COMMIT();

    int buf = 0;
    for (int kt = 0; kt < NK64; kt++) {
        unsigned cur = sb + buf * STAGE_BYTES;
        int nb = buf + 2; if (nb >= 3) nb -= 3;
        if (kt + 2 < NK64)
            load_stage(sb + nb * STAGE_BYTES, kt + 2, m0, n0, M, tid);
        CP_COMMIT();
        CP_WAIT2();
        __syncthreads();

#pragma unroll
        for (int ks = 0; ks < 4; ks++) {
            unsigned a[2][4], b[4][4];
            unsigned acb = ks * 32 + a_cb;
#pragma unroll
            for (int mf = 0; mf < 2; mf++)
                ldsm4(a[mf], cur + SW((a_row + mf * 16) * 128 + acb));
            unsigned bcb = ks * 32 + b_cb;
#pragma unroll
            for (int f = 0; f < 4; f++)
                ldsm4(b[f], cur + TB_OFF + SW((b_rowbase + f * 16) * 128 + bcb));
#pragma unroll
            for (int mf = 0; mf < 2; mf++)
#pragma unroll
                for (int f = 0; f < 4; f++) {
                    mma16816(acc[mf][2 * f],     a[mf], &b[f][0]);
                    mma16816(acc[mf][2 * f + 1], a[mf], &b[f][2]);
                }
        }
        __syncthreads();
        buf++; if (buf == 3) buf = 0;
    }

#pragma unroll
    for (int mf = 0; mf < 2; mf++) {
        int r0 = m0 + wm + mf * 16 + gID;
#pragma unroll
        for (int nf = 0; nf < 8; nf++) {
            int col = n0 + wn + nf * 8 + tig * 2;
            if (r0 < M) {
                __half2 h = __floats2half2_rn(acc[mf][nf][0], acc[mf][nf][1]);
                *(unsigned*)&g_h1h[(long long)r0 * HID + col] = *(unsigned*)&h;
            }
            if (r0 + 8 < M) {
                __half2 h = __floats2half2_rn(acc[mf][nf][2], acc[mf][nf][3]);
                *(unsigned*)&g_h1h[(long long)(r0 + 8) * HID + col] = *(unsigned*)&h;
            }
        }
    }
}

// ---------------- SpMM1: r1 = relu( dinv_d * (sum dinv_s h1[s]) + b1 ) ---
// one block of 128 threads per dst row; fp16 in, fp16 out
__global__ void k_spmm1(const float* __restrict__ b1) {
    int row = blockIdx.x;
    int c = threadIdx.x << 2;
    float di = g_dinv[row];

    uint2 u0 = *(const uint2*)&g_h1h[(long long)row * HID + c];
    float2 vlo = __half22float2(*(__half2*)&u0.x);
    float2 vhi = __half22float2(*(__half2*)&u0.y);
    float4 acc;
    acc.x = di * vlo.x; acc.y = di * vlo.y; acc.z = di * vhi.x; acc.w = di * vhi.y;

    int p0 = g_rowptr[row], p1 = g_rowptr[row + 1];
    for (int p = p0; p < p1; ++p) {
        int s = g_col[p];
        float w = g_dinv[s];
        uint2 u = *(const uint2*)&g_h1h[(long long)s * HID + c];
        float2 a = __half22float2(*(__half2*)&u.x);
        float2 b = __half22float2(*(__half2*)&u.y);
        acc.x += w * a.x; acc.y += w * a.y; acc.z += w * b.x; acc.w += w * b.y;
    }
    float4 bb = *(const float4*)&b1[c];
    acc.x = fmaxf(acc.x * di + bb.x, 0.f);
    acc.y = fmaxf(acc.y * di + bb.y, 0.f);
    acc.z = fmaxf(acc.z * di + bb.z, 0.f);
    acc.w = fmaxf(acc.w * di + bb.w, 0.f);
    __half2 hlo = __floats2half2_rn(acc.x, acc.y);
    __half2 hhi = __floats2half2_rn(acc.z, acc.w);
    uint2 uo;
    uo.x = *(unsigned*)&hlo; uo.y = *(unsigned*)&hhi;
    *(uint2*)&g_r1h[(long long)row * HID + c] = uo;
}

// ---------------- GEMM2: h2 = r1 @ W2  (fp16 r1, fp32 acc) --------------
__global__ void k_gemm2(const float* __restrict__ W2, int Nn) {
    __shared__ float w[HID * NCLS];
    for (int i = threadIdx.x; i < HID * NCLS; i += blockDim.x) w[i] = W2[i];
    __syncthreads();
    int row = blockIdx.x * blockDim.x + threadIdx.x;
    if (row >= Nn) return;
    float acc[NCLS];
#pragma unroll
    for (int j = 0; j < NCLS; j++) acc[j] = 0.f;
    const uint4* xr = (const uint4*)&g_r1h[(long long)row * HID];
#pragma unroll 4
    for (int k8 = 0; k8 < HID / 8; k8++) {
        uint4 u = xr[k8];
        float2 f0 = __half22float2(*(__half2*)&u.x);
        float2 f1 = __half22float2(*(__half2*)&u.y);
        float2 f2 = __half22float2(*(__half2*)&u.z);
        float2 f3 = __half22float2(*(__half2*)&u.w);
        const float* w0 = &w[(k8 * 8) * NCLS];
#pragma unroll
        for (int j = 0; j < NCLS; j++)
            acc[j] += f0.x * w0[j]            + f0.y * w0[NCLS + j] +
                      f1.x * w0[2 * NCLS + j] + f1.y * w0[3 * NCLS + j] +
                      f2.x * w0[4 * NCLS + j] + f2.y * w0[5 * NCLS + j] +
                      f3.x * w0[6 * NCLS + j] + f3.y * w0[7 * NCLS + j];
    }
#pragma unroll
    for (int j = 0; j < NCLS; j++) g_h2[(long long)row * NCLS + j] = acc[j];
}

// ---------------- SpMM2 + bias + log_softmax (warp per row) -------------
__global__ void k_spmm2(const float* __restrict__ b2, float* __restrict__ out, int Nn) {
    int row = (blockIdx.x * blockDim.x + threadIdx.x) >> 5;
    int lane = threadIdx.x & 31;
    if (row >= Nn) return;

    float di = g_dinv[row];
    float acc = 0.f;
    if (lane < NCLS) acc = di * g_h2[(long long)row * NCLS + lane];

    int p0 = g_rowptr[row], p1 = g_rowptr[row + 1];
    for (int p = p0; p < p1; ++p) {
        int s = g_col[p];
        float w = g_dinv[s];
        if (lane < NCLS) acc += w * g_h2[(long long)s * NCLS + lane];
    }
    acc = acc * di + ((lane < NCLS) ? b2[lane] : 0.f);

    float v = (lane < NCLS) ? acc : -3.4e38f;
#pragma unroll
    for (int o = 16; o > 0; o >>= 1) v = fmaxf(v, __shfl_xor_sync(0xffffffffu, v, o));
    float ex = (lane < NCLS) ? expf(acc - v) : 0.f;
#pragma unroll
    for (int o = 16; o > 0; o >>= 1) ex += __shfl_xor_sync(0xffffffffu, ex, o);
    float lse = logf(ex);
    if (lane < NCLS) out[(long long)row * NCLS + lane] = acc - v - lse;
}

// ---------------- launch ---------------------------------------------------
extern "C" void kernel_launch(void* const* d_in, const int* in_sizes, int n_in,
                              void* d_out, int out_size) {
    const float* x  = (const float*)d_in[0];
    const int*   ei = (const int*)d_in[1];
    const float* W1 = (const float*)d_in[2];
    const float* b1 = (const float*)d_in[3];
    const float* W2 = (const float*)d_in[4];
    const float* b2 = (const float*)d_in[5];
    float* out = (float*)d_out;

    int Nn = in_sizes[0] / IN_F;          // 20000
    int E  = in_sizes[1] / 2;

    static cudaStream_t s2 = 0;
    static cudaEvent_t evFork = 0, evJoin = 0;
    if (s2 == 0) {
        cudaStreamCreateWithFlags(&s2, cudaStreamNonBlocking);
        cudaEventCreateWithFlags(&evFork, cudaEventDisableTiming);
        cudaEventCreateWithFlags(&evJoin, cudaEventDisableTiming);
    }

    // detect on main stream, then fork the graph-build chain onto s2
    k_detect<<<1, 256>>>(ei, E);
    cudaEventRecord(evFork, 0);
    cudaStreamWaitEvent(s2, evFork, 0);

    // side chain: degree -> scan -> csr fill
    k_zero     <<<(Nn + 255) / 256, 256, 0, s2>>>(Nn);
    k_count    <<<(E + 255) / 256, 256, 0, s2>>>(ei, E);
    k_scan_dinv<<<1 + (Nn + 1023) / 1024, 1024, 0, s2>>>(Nn);
    k_fill     <<<(E + 255) / 256, 256, 0, s2>>>(ei, E);
    cudaEventRecord(evJoin, s2);

    // main chain: convert + GEMM1
    long long total4 = (long long)Nn * IN_F / 4;
    int nConvA = (int)((total4 + 255) / 256);
    k_conv<<<nConvA + 2048, 256>>>(x, W1, total4, nConvA);

    cudaFuncSetAttribute(k_gemm1_f16, cudaFuncAttributeMaxDynamicSharedMemorySize,
                         GSMEM_TOTAL);
    dim3 g1(HID / 128, (Nn + 127) / 128);   // (4, 157)
    k_gemm1_f16<<<g1, 256, GSMEM_TOTAL>>>(Nn);

    // join: SpMM1 needs both GEMM1 (stream 0) and CSR/dinv (s2)
    cudaStreamWaitEvent(0, evJoin, 0);
    k_spmm1<<<Nn, 128>>>(b1);
    k_gemm2<<<(Nn + 127) / 128, 128>>>(W2, Nn);
    k_spmm2<<<(Nn * 32 + 127) / 128, 128>>>(b2, out, Nn);
}